// round 8
// baseline (speedup 1.0000x reference)
#include <cuda_runtime.h>
#include <cuda_bf16.h>
#include <cuda_fp16.h>
#include <math.h>
#include <stdint.h>

#define N_NODES_MAX 100000
#define NEG_SLOPE 0.2f

// ---------------- scratch (device globals: alloc-free) ----------------
__device__ float    g_el[N_NODES_MAX * 4];
__device__ float    g_er[N_NODES_MAX * 4];
__device__ int      g_offs[N_NODES_MAX + 1];
__device__ uint32_t g_fth[N_NODES_MAX * 64];  // fp16 ft rows: 64 uint32 = 128 half
__device__ uint4    g_Bhi4[2048];             // fp16 B[n][k] hi image (128x128 = 32KB)
__device__ uint4    g_Blo4[2048];             // fp16 B[n][k] lo image (32KB)

__device__ __forceinline__ uint32_t smem_u32(const void* p) {
    uint32_t a;
    asm("{ .reg .u64 t; cvta.to.shared.u64 t, %1; cvt.u32.u64 %0, t; }" : "=r"(a) : "l"(p));
    return a;
}

#define LDM4(r, addr) \
    asm volatile("ldmatrix.sync.aligned.m8n8.x4.shared.b16 {%0,%1,%2,%3}, [%4];" \
        : "=r"((r)[0]), "=r"((r)[1]), "=r"((r)[2]), "=r"((r)[3]) : "r"(addr))

#define MMA_F16(c, a, b) \
    asm volatile("mma.sync.aligned.m16n8k16.row.col.f32.f16.f16.f32 " \
        "{%0,%1,%2,%3}, {%4,%5,%6,%7}, {%8,%9}, {%0,%1,%2,%3};" \
        : "+f"((c)[0]), "+f"((c)[1]), "+f"((c)[2]), "+f"((c)[3]) \
        : "r"((a)[0]), "r"((a)[1]), "r"((a)[2]), "r"((a)[3]), "r"((b)[0]), "r"((b)[1]))

// smem: padded rows of 136 half = 272 B (17x16B -> conflict-free ldmatrix)
#define ROWB 272
#define SA    0
#define SB_HI (SA + 128 * ROWB)
#define SB_LO (SB_HI + 128 * ROWB)
#define SM_TOTAL (SB_LO + 128 * ROWB)   // 104448 B -> 2 CTAs/SM

// ---------------- 0) prep: W[k][n] -> fp16 hi/lo B[n][k] images ----------------
__global__ void prepB_kernel(const float* __restrict__ W) {
    int idx = blockIdx.x * blockDim.x + threadIdx.x;
    if (idx >= 16384) return;
    int k = idx >> 7, n = idx & 127;
    float x = W[idx];
    __half hi = __float2half_rn(x);
    __half lo = __float2half_rn(x - __half2float(hi));
    ((__half*)g_Bhi4)[n * 128 + k] = hi;
    ((__half*)g_Blo4)[n * 128 + k] = lo;
}

// ---------------- 1) mma.sync 2-term fp16 GEMM + fused fp16-ft / el / er --------
__global__ __launch_bounds__(256) void gemm_mma_kernel(const float* __restrict__ A,
                                                       const float* __restrict__ attn_l,
                                                       const float* __restrict__ attn_r,
                                                       int M) {
    extern __shared__ char smem[];
    const uint32_t sb = smem_u32(smem);
    const int tid = threadIdx.x, wid = tid >> 5, lane = tid & 31;
    const int bm = blockIdx.x * 128;

    // stage B hi/lo: 2048 uint4 per image, 16 uint4 (256B) per packed row
    for (int i = tid; i < 2048; i += 256) {
        int row = i >> 4, c = i & 15;
        *(uint4*)(smem + SB_HI + row * ROWB + c * 16) = g_Bhi4[i];
        *(uint4*)(smem + SB_LO + row * ROWB + c * 16) = g_Blo4[i];
    }
    // stage A: fp32 -> fp16 (single term)
#pragma unroll 4
    for (int it = 0; it < 16; it++) {
        int idx = tid + it * 256;            // 0..4095 (128 rows x 32 float4)
        int row = idx >> 5, c4 = (idx & 31) * 4;
        float4 v = make_float4(0.f, 0.f, 0.f, 0.f);
        if (bm + row < M) v = *(const float4*)(A + (size_t)(bm + row) * 128 + c4);
        __half2 hA = __floats2half2_rn(v.x, v.y);
        __half2 hB = __floats2half2_rn(v.z, v.w);
        *(uint2*)(smem + SA + row * ROWB + c4 * 2) = make_uint2(*(uint32_t*)&hA, *(uint32_t*)&hB);
    }
    __syncthreads();

    const int wm = wid & 3, wn = wid >> 2;
    const int m0 = wm * 32, n0 = wn * 64;

    float acc[2][8][4];
#pragma unroll
    for (int i = 0; i < 2; i++)
#pragma unroll
        for (int j = 0; j < 8; j++)
#pragma unroll
            for (int q = 0; q < 4; q++) acc[i][j][q] = 0.f;

    // ldmatrix per-lane base addresses
    const uint32_t a_row = m0 + (lane & 15);
    const uint32_t a_off = a_row * ROWB + ((lane >> 4) << 4);
    const uint32_t b_row = n0 + (lane & 7) + ((lane >> 4) << 3);
    const uint32_t b_off = b_row * ROWB + (((lane >> 3) & 1) << 4);
    const uint32_t a_b  = sb + SA + a_off;
    const uint32_t bh_b = sb + SB_HI + b_off, bl_b = sb + SB_LO + b_off;

#pragma unroll 1
    for (int ks = 0; ks < 8; ks++) {
        const uint32_t k0b = ks * 32;   // 16 cols * 2B
        uint32_t av[2][4], bh[8][2], bl[8][2];
        LDM4(av[0], a_b + k0b);
        LDM4(av[1], a_b + 16 * ROWB + k0b);
#pragma unroll
        for (int jj = 0; jj < 4; jj++) {
            uint32_t r[4];
            LDM4(r, bh_b + jj * 16 * ROWB + k0b);
            bh[2 * jj][0] = r[0]; bh[2 * jj][1] = r[1];
            bh[2 * jj + 1][0] = r[2]; bh[2 * jj + 1][1] = r[3];
            LDM4(r, bl_b + jj * 16 * ROWB + k0b);
            bl[2 * jj][0] = r[0]; bl[2 * jj][1] = r[1];
            bl[2 * jj + 1][0] = r[2]; bl[2 * jj + 1][1] = r[3];
        }
#pragma unroll
        for (int im = 0; im < 2; im++)
#pragma unroll
            for (int jn = 0; jn < 8; jn++) {
                MMA_F16(acc[im][jn], av[im], bh[jn]);   // A * B_hi
                MMA_F16(acc[im][jn], av[im], bl[jn]);   // A * B_lo
            }
    }

    // epilogue: fp16 ft + exact el/er (quad owns full 32-col head dot)
    float alv[16], arv[16];
#pragma unroll
    for (int j = 0; j < 8; j++) {
        int c0 = n0 + j * 8 + 2 * (lane & 3);
        alv[2 * j] = __ldg(attn_l + c0); alv[2 * j + 1] = __ldg(attn_l + c0 + 1);
        arv[2 * j] = __ldg(attn_r + c0); arv[2 * j + 1] = __ldg(attn_r + c0 + 1);
    }
    const int hA = n0 >> 5;            // heads hA, hA+1
#pragma unroll
    for (int im = 0; im < 2; im++) {
#pragma unroll
        for (int hf = 0; hf < 2; hf++) {
            int row = bm + m0 + im * 16 + (lane >> 2) + hf * 8;
            float sA = 0.f, sB = 0.f, rA = 0.f, rB = 0.f;
            uint32_t pk[8];
#pragma unroll
            for (int j = 0; j < 8; j++) {
                float v0 = acc[im][j][hf * 2], v1 = acc[im][j][hf * 2 + 1];
                __half2 hh = __floats2half2_rn(v0, v1);
                pk[j] = *(uint32_t*)&hh;
                if (j < 4) {
                    sA = fmaf(v0, alv[2 * j], fmaf(v1, alv[2 * j + 1], sA));
                    rA = fmaf(v0, arv[2 * j], fmaf(v1, arv[2 * j + 1], rA));
                } else {
                    sB = fmaf(v0, alv[2 * j], fmaf(v1, alv[2 * j + 1], sB));
                    rB = fmaf(v0, arv[2 * j], fmaf(v1, arv[2 * j + 1], rB));
                }
            }
            if (row < M) {
                uint32_t* dst = g_fth + (size_t)row * 64 + (n0 >> 1) + (lane & 3);
#pragma unroll
                for (int j = 0; j < 8; j++) dst[j * 4] = pk[j];
            }
            sA += __shfl_xor_sync(~0u, sA, 1); sA += __shfl_xor_sync(~0u, sA, 2);
            sB += __shfl_xor_sync(~0u, sB, 1); sB += __shfl_xor_sync(~0u, sB, 2);
            rA += __shfl_xor_sync(~0u, rA, 1); rA += __shfl_xor_sync(~0u, rA, 2);
            rB += __shfl_xor_sync(~0u, rB, 1); rB += __shfl_xor_sync(~0u, rB, 2);
            if ((lane & 3) == 0 && row < M) {
                g_el[row * 4 + hA]     = sA;
                g_el[row * 4 + hA + 1] = sB;
                g_er[row * 4 + hA]     = rA;
                g_er[row * 4 + hA + 1] = rB;
            }
        }
    }
}

// ---------------- 2) CSR offsets from sorted dst (binary search) ----------------
__global__ void offs_kernel(const int* __restrict__ dst, int N, int E) {
    int n = blockIdx.x * blockDim.x + threadIdx.x;
    if (n > N) return;
    int lo = 0, hi = E;
    while (lo < hi) {
        int mid = (lo + hi) >> 1;
        if (__ldg(dst + mid) < n) lo = mid + 1; else hi = mid;
    }
    g_offs[n] = lo;
}

// ---------------- 3) aggregation: 1 warp/node, batch-8 edges, MLP-8 gather -----
// Phase A: 8 edges scored at once (lane = edge(lane>>2) x head(lane&3)).
// Phase B: all 8 ft LDG.64 hoisted before consumers -> 8 loads in flight.
__global__ __launch_bounds__(256) void agg_kernel(const int* __restrict__ src,
                                                  float* __restrict__ out, int N) {
    int gid  = blockIdx.x * blockDim.x + threadIdx.x;
    int node = gid >> 5;
    int lane = gid & 31;
    if (node >= N) return;

    const int j  = lane >> 2;   // edge slot 0..7
    const int hh = lane & 3;    // head for phase A
    int s = g_offs[node];
    int e = g_offs[node + 1];
    float er_l = g_er[node * 4 + hh];

    float psum = 0.f;
    float a0 = 0.f, a1 = 0.f, a2 = 0.f, a3 = 0.f;
    const uint2* ft = (const uint2*)g_fth;   // 32 uint2 per row

    for (int i0 = s; i0 < e; i0 += 8) {
        const int c = e - i0;                // >= 1
        // phase A: score up to 8 edges
        int sn = 0; float p = 0.f;
        if (j < c) {
            sn = __ldg(src + i0 + j);
            float sc = __ldg(&g_el[sn * 4 + hh]) + er_l;
            sc = fmaxf(sc, NEG_SLOPE * sc);
            p = __expf(sc);                  // |sc| small: no max shift needed
            psum += p;
        }
        // phase B: hoisted gather (8 independent LDG.64 in flight)
        uint2 v[8]; float pj[8];
#pragma unroll
        for (int t = 0; t < 8; t++) {
            uint2 vv = make_uint2(0u, 0u);
            float pp = 0.f;
            if (t < c) {
                int snj = __shfl_sync(~0u, sn, t << 2);
                pp = __shfl_sync(~0u, p, (t << 2) | (lane >> 3));
                vv = __ldg(&ft[(size_t)snj * 32 + lane]);
            }
            v[t] = vv; pj[t] = pp;
        }
#pragma unroll
        for (int t = 0; t < 8; t++) {
            float2 f01 = __half22float2(*(__half2*)&v[t].x);
            float2 f23 = __half22float2(*(__half2*)&v[t].y);
            a0 = fmaf(pj[t], f01.x, a0);
            a1 = fmaf(pj[t], f01.y, a1);
            a2 = fmaf(pj[t], f23.x, a2);
            a3 = fmaf(pj[t], f23.y, a3);
        }
    }

    // per-head sums: combine the 8 lanes sharing head (lane&3)
    psum += __shfl_xor_sync(~0u, psum, 4);
    psum += __shfl_xor_sync(~0u, psum, 8);
    psum += __shfl_xor_sync(~0u, psum, 16);
    float hsum = __shfl_sync(~0u, psum, lane >> 3);   // head of my features
    float inv = (hsum > 0.f) ? (1.f / hsum) : 0.f;

    *(float4*)(out + (size_t)node * 128 + lane * 4) =
        make_float4(a0 * inv, a1 * inv, a2 * inv, a3 * inv);
}

// ---------------- launch ----------------
extern "C" void kernel_launch(void* const* d_in, const int* in_sizes, int n_in,
                              void* d_out, int out_size) {
    const float* feat   = (const float*)d_in[0];
    const int*   src    = (const int*)d_in[1];
    const int*   dst    = (const int*)d_in[2];
    const float* W      = (const float*)d_in[3];
    const float* attn_l = (const float*)d_in[4];
    const float* attn_r = (const float*)d_in[5];
    float* out = (float*)d_out;

    int M = in_sizes[0] / 128;   // nodes
    int E = in_sizes[1];         // edges

    cudaFuncSetAttribute(gemm_mma_kernel, cudaFuncAttributeMaxDynamicSharedMemorySize, SM_TOTAL);

    prepB_kernel<<<64, 256>>>(W);
    offs_kernel<<<(M + 1 + 255) / 256, 256>>>(dst, M, E);
    gemm_mma_kernel<<<(M + 127) / 128, 256, SM_TOTAL>>>(feat, attn_l, attn_r, M);
    agg_kernel<<<((size_t)M * 32 + 255) / 256, 256>>>(src, out, M);
}

// round 9
// speedup vs baseline: 1.0992x; 1.0992x over previous
#include <cuda_runtime.h>
#include <cuda_bf16.h>
#include <cuda_fp16.h>
#include <math.h>
#include <stdint.h>

#define N_NODES_MAX 100000
#define NEG_SLOPE 0.2f

// ---------------- scratch (device globals: alloc-free) ----------------
__device__ float    g_el[N_NODES_MAX * 4];
__device__ float    g_er[N_NODES_MAX * 4];
__device__ int      g_offs[N_NODES_MAX + 1];
__device__ uint32_t g_fth[N_NODES_MAX * 64];  // fp16 ft rows: 64 uint32 = 128 half
__device__ uint4    g_Bhi4[2048];             // fp16 B[n][k] hi image (128x128 = 32KB)
__device__ uint4    g_Blo4[2048];             // fp16 B[n][k] lo image (32KB)

__device__ __forceinline__ uint32_t smem_u32(const void* p) {
    uint32_t a;
    asm("{ .reg .u64 t; cvta.to.shared.u64 t, %1; cvt.u32.u64 %0, t; }" : "=r"(a) : "l"(p));
    return a;
}

#define LDM4(r, addr) \
    asm volatile("ldmatrix.sync.aligned.m8n8.x4.shared.b16 {%0,%1,%2,%3}, [%4];" \
        : "=r"((r)[0]), "=r"((r)[1]), "=r"((r)[2]), "=r"((r)[3]) : "r"(addr))

#define MMA_F16(c, a, b) \
    asm volatile("mma.sync.aligned.m16n8k16.row.col.f32.f16.f16.f32 " \
        "{%0,%1,%2,%3}, {%4,%5,%6,%7}, {%8,%9}, {%0,%1,%2,%3};" \
        : "+f"((c)[0]), "+f"((c)[1]), "+f"((c)[2]), "+f"((c)[3]) \
        : "r"((a)[0]), "r"((a)[1]), "r"((a)[2]), "r"((a)[3]), "r"((b)[0]), "r"((b)[1]))

// smem: padded rows of 136 half = 272 B (17x16B -> conflict-free ldmatrix)
#define ROWB 272
#define SA    0
#define SB_HI (SA + 128 * ROWB)
#define SB_LO (SB_HI + 128 * ROWB)
#define SM_TOTAL (SB_LO + 128 * ROWB)   // 104448 B -> 2 CTAs/SM

// ---------------- 0) prep: W[k][n] -> fp16 hi/lo B[n][k] images ----------------
__global__ void prepB_kernel(const float* __restrict__ W) {
    int idx = blockIdx.x * blockDim.x + threadIdx.x;
    if (idx >= 16384) return;
    int k = idx >> 7, n = idx & 127;
    float x = W[idx];
    __half hi = __float2half_rn(x);
    __half lo = __float2half_rn(x - __half2float(hi));
    ((__half*)g_Bhi4)[n * 128 + k] = hi;
    ((__half*)g_Blo4)[n * 128 + k] = lo;
}

// ---------------- 1) mma.sync 2-term fp16 GEMM + fused fp16-ft / el / er --------
__global__ __launch_bounds__(256, 2) void gemm_mma_kernel(const float* __restrict__ A,
                                                          const float* __restrict__ attn_l,
                                                          const float* __restrict__ attn_r,
                                                          int M) {
    extern __shared__ char smem[];
    const uint32_t sb = smem_u32(smem);
    const int tid = threadIdx.x, wid = tid >> 5, lane = tid & 31;
    const int bm = blockIdx.x * 128;

    // stage B hi/lo: 2048 uint4 per image, 16 uint4 (256B) per packed row
    for (int i = tid; i < 2048; i += 256) {
        int row = i >> 4, c = i & 15;
        *(uint4*)(smem + SB_HI + row * ROWB + c * 16) = g_Bhi4[i];
        *(uint4*)(smem + SB_LO + row * ROWB + c * 16) = g_Blo4[i];
    }
    // stage A: fp32 -> fp16 (single term)
#pragma unroll 4
    for (int it = 0; it < 16; it++) {
        int idx = tid + it * 256;            // 0..4095 (128 rows x 32 float4)
        int row = idx >> 5, c4 = (idx & 31) * 4;
        float4 v = make_float4(0.f, 0.f, 0.f, 0.f);
        if (bm + row < M) v = *(const float4*)(A + (size_t)(bm + row) * 128 + c4);
        __half2 hA = __floats2half2_rn(v.x, v.y);
        __half2 hB = __floats2half2_rn(v.z, v.w);
        *(uint2*)(smem + SA + row * ROWB + c4 * 2) = make_uint2(*(uint32_t*)&hA, *(uint32_t*)&hB);
    }
    __syncthreads();

    const int wm = wid & 3, wn = wid >> 2;
    const int m0 = wm * 32, n0 = wn * 64;

    float acc[2][8][4];
#pragma unroll
    for (int i = 0; i < 2; i++)
#pragma unroll
        for (int j = 0; j < 8; j++)
#pragma unroll
            for (int q = 0; q < 4; q++) acc[i][j][q] = 0.f;

    // ldmatrix per-lane base addresses
    const uint32_t a_row = m0 + (lane & 15);
    const uint32_t a_off = a_row * ROWB + ((lane >> 4) << 4);
    const uint32_t b_row = n0 + (lane & 7) + ((lane >> 4) << 3);
    const uint32_t b_off = b_row * ROWB + (((lane >> 3) & 1) << 4);
    const uint32_t a_b  = sb + SA + a_off;
    const uint32_t bh_b = sb + SB_HI + b_off, bl_b = sb + SB_LO + b_off;

#pragma unroll
    for (int ks = 0; ks < 8; ks++) {
        const uint32_t k0b = ks * 32;   // 16 cols * 2B
        uint32_t av[2][4], bh[8][2], bl[8][2];
        LDM4(av[0], a_b + k0b);
        LDM4(av[1], a_b + 16 * ROWB + k0b);
#pragma unroll
        for (int jj = 0; jj < 4; jj++) {
            uint32_t r[4];
            LDM4(r, bh_b + jj * 16 * ROWB + k0b);
            bh[2 * jj][0] = r[0]; bh[2 * jj][1] = r[1];
            bh[2 * jj + 1][0] = r[2]; bh[2 * jj + 1][1] = r[3];
            LDM4(r, bl_b + jj * 16 * ROWB + k0b);
            bl[2 * jj][0] = r[0]; bl[2 * jj][1] = r[1];
            bl[2 * jj + 1][0] = r[2]; bl[2 * jj + 1][1] = r[3];
        }
#pragma unroll
        for (int im = 0; im < 2; im++)
#pragma unroll
            for (int jn = 0; jn < 8; jn++) {
                MMA_F16(acc[im][jn], av[im], bh[jn]);   // A * B_hi
                MMA_F16(acc[im][jn], av[im], bl[jn]);   // A * B_lo
            }
    }

    // epilogue: fp16 ft + exact el/er (quad owns full 32-col head dot)
    float alv[16], arv[16];
#pragma unroll
    for (int j = 0; j < 8; j++) {
        int c0 = n0 + j * 8 + 2 * (lane & 3);
        alv[2 * j] = __ldg(attn_l + c0); alv[2 * j + 1] = __ldg(attn_l + c0 + 1);
        arv[2 * j] = __ldg(attn_r + c0); arv[2 * j + 1] = __ldg(attn_r + c0 + 1);
    }
    const int hA = n0 >> 5;            // heads hA, hA+1
#pragma unroll
    for (int im = 0; im < 2; im++) {
#pragma unroll
        for (int hf = 0; hf < 2; hf++) {
            int row = bm + m0 + im * 16 + (lane >> 2) + hf * 8;
            float sA = 0.f, sB = 0.f, rA = 0.f, rB = 0.f;
            uint32_t pk[8];
#pragma unroll
            for (int j = 0; j < 8; j++) {
                float v0 = acc[im][j][hf * 2], v1 = acc[im][j][hf * 2 + 1];
                __half2 hh = __floats2half2_rn(v0, v1);
                pk[j] = *(uint32_t*)&hh;
                if (j < 4) {
                    sA = fmaf(v0, alv[2 * j], fmaf(v1, alv[2 * j + 1], sA));
                    rA = fmaf(v0, arv[2 * j], fmaf(v1, arv[2 * j + 1], rA));
                } else {
                    sB = fmaf(v0, alv[2 * j], fmaf(v1, alv[2 * j + 1], sB));
                    rB = fmaf(v0, arv[2 * j], fmaf(v1, arv[2 * j + 1], rB));
                }
            }
            if (row < M) {
                uint32_t* dst = g_fth + (size_t)row * 64 + (n0 >> 1) + (lane & 3);
#pragma unroll
                for (int j = 0; j < 8; j++) dst[j * 4] = pk[j];
            }
            sA += __shfl_xor_sync(~0u, sA, 1); sA += __shfl_xor_sync(~0u, sA, 2);
            sB += __shfl_xor_sync(~0u, sB, 1); sB += __shfl_xor_sync(~0u, sB, 2);
            rA += __shfl_xor_sync(~0u, rA, 1); rA += __shfl_xor_sync(~0u, rA, 2);
            rB += __shfl_xor_sync(~0u, rB, 1); rB += __shfl_xor_sync(~0u, rB, 2);
            if ((lane & 3) == 0 && row < M) {
                g_el[row * 4 + hA]     = sA;
                g_el[row * 4 + hA + 1] = sB;
                g_er[row * 4 + hA]     = rA;
                g_er[row * 4 + hA + 1] = rB;
            }
        }
    }
}

// ---------------- 2) CSR offsets from sorted dst (binary search) ----------------
__global__ void offs_kernel(const int* __restrict__ dst, int N, int E) {
    int n = blockIdx.x * blockDim.x + threadIdx.x;
    if (n > N) return;
    int lo = 0, hi = E;
    while (lo < hi) {
        int mid = (lo + hi) >> 1;
        if (__ldg(dst + mid) < n) lo = mid + 1; else hi = mid;
    }
    g_offs[n] = lo;
}

// ---------------- 3) aggregation: 1 warp/node, quarter-warp per edge -----------
// 8 lanes per edge, 4 edges/iter. Lane's feature slice (16 feats) belongs to the
// SAME head it scores: h = (lane&7)>>1. No shuffles in the loop; one xor8+xor16
// reduction per node at the end. 8 independent LDG.128 in flight per iteration.
__global__ __launch_bounds__(256) void agg_kernel(const int* __restrict__ src,
                                                  float* __restrict__ out, int N) {
    int gid  = blockIdx.x * blockDim.x + threadIdx.x;
    int node = gid >> 5;
    int lane = gid & 31;
    if (node >= N) return;

    const int q  = lane >> 3;        // edge slot 0..3
    const int sl = lane & 7;         // feature slice: [16*sl, 16*sl+16)
    const int hh = sl >> 1;          // head of this slice (and of the score)

    int s = g_offs[node];
    int e = g_offs[node + 1];
    float er_h = g_er[node * 4 + hh];

    float psum = 0.f;
    float acc[16];
#pragma unroll
    for (int t = 0; t < 16; t++) acc[t] = 0.f;

    const uint4* ft = (const uint4*)g_fth;   // 16 uint4 per row
    const uint4 z4 = make_uint4(0u, 0u, 0u, 0u);

    for (int i0 = s; i0 < e; i0 += 4) {
        int i = i0 + q;
        bool ok = i < e;
        int sn = 0; float p = 0.f;
        if (ok) {
            sn = __ldg(src + i);
            float sc = __ldg(&g_el[sn * 4 + hh]) + er_h;
            sc = fmaxf(sc, NEG_SLOPE * sc);   // leaky relu
            p = __expf(sc);                   // |sc| small: no max shift needed
            psum += p;
        }
        uint4 v0 = z4, v1 = z4;
        if (ok) {
            const uint4* row = &ft[(size_t)sn * 16 + sl * 2];
            v0 = __ldg(row);
            v1 = __ldg(row + 1);
        }
        const __half2* h0 = (const __half2*)&v0;
        const __half2* h1 = (const __half2*)&v1;
#pragma unroll
        for (int t = 0; t < 4; t++) {
            float2 f = __half22float2(h0[t]);
            acc[2 * t]     = fmaf(p, f.x, acc[2 * t]);
            acc[2 * t + 1] = fmaf(p, f.y, acc[2 * t + 1]);
        }
#pragma unroll
        for (int t = 0; t < 4; t++) {
            float2 f = __half22float2(h1[t]);
            acc[8 + 2 * t]     = fmaf(p, f.x, acc[8 + 2 * t]);
            acc[8 + 2 * t + 1] = fmaf(p, f.y, acc[8 + 2 * t + 1]);
        }
    }

    // combine the 4 quarter-warps (same sl/hh, different edge slots)
    psum += __shfl_xor_sync(~0u, psum, 8);
    psum += __shfl_xor_sync(~0u, psum, 16);
#pragma unroll
    for (int t = 0; t < 16; t++) {
        acc[t] += __shfl_xor_sync(~0u, acc[t], 8);
        acc[t] += __shfl_xor_sync(~0u, acc[t], 16);
    }

    if (q == 0) {
        float inv = (psum > 0.f) ? (1.f / psum) : 0.f;
        float* dst = out + (size_t)node * 128 + sl * 16;
#pragma unroll
        for (int t = 0; t < 4; t++)
            *(float4*)(dst + 4 * t) = make_float4(acc[4 * t] * inv, acc[4 * t + 1] * inv,
                                                  acc[4 * t + 2] * inv, acc[4 * t + 3] * inv);
    }
}

// ---------------- launch ----------------
extern "C" void kernel_launch(void* const* d_in, const int* in_sizes, int n_in,
                              void* d_out, int out_size) {
    const float* feat   = (const float*)d_in[0];
    const int*   src    = (const int*)d_in[1];
    const int*   dst    = (const int*)d_in[2];
    const float* W      = (const float*)d_in[3];
    const float* attn_l = (const float*)d_in[4];
    const float* attn_r = (const float*)d_in[5];
    float* out = (float*)d_out;

    int M = in_sizes[0] / 128;   // nodes
    int E = in_sizes[1];         // edges

    cudaFuncSetAttribute(gemm_mma_kernel, cudaFuncAttributeMaxDynamicSharedMemorySize, SM_TOTAL);

    prepB_kernel<<<64, 256>>>(W);
    offs_kernel<<<(M + 1 + 255) / 256, 256>>>(dst, M, E);
    gemm_mma_kernel<<<(M + 127) / 128, 256, SM_TOTAL>>>(feat, attn_l, attn_r, M);
    agg_kernel<<<((size_t)M * 32 + 255) / 256, 256>>>(src, out, M);
}

// round 10
// speedup vs baseline: 1.2306x; 1.1195x over previous
#include <cuda_runtime.h>
#include <cuda_bf16.h>
#include <cuda_fp16.h>
#include <math.h>
#include <stdint.h>

#define N_NODES_MAX 100000
#define NEG_SLOPE 0.2f
#define LOG2E 1.4426950408889634f

// ---------------- scratch (device globals: alloc-free) ----------------
__device__ float    g_el[N_NODES_MAX * 4];    // pre-scaled by LOG2E
__device__ float    g_er[N_NODES_MAX * 4];    // pre-scaled by LOG2E
__device__ int      g_offs[N_NODES_MAX + 1];
__device__ uint32_t g_fth[N_NODES_MAX * 64];  // fp16 ft rows: 64 uint32 = 128 half
__device__ uint4    g_Bhi4[2048];             // fp16 B[n][k] hi image (128x128 = 32KB)
__device__ uint4    g_Blo4[2048];             // fp16 B[n][k] lo image (32KB)

__device__ __forceinline__ uint32_t smem_u32(const void* p) {
    uint32_t a;
    asm("{ .reg .u64 t; cvta.to.shared.u64 t, %1; cvt.u32.u64 %0, t; }" : "=r"(a) : "l"(p));
    return a;
}

#define LDM4(r, addr) \
    asm volatile("ldmatrix.sync.aligned.m8n8.x4.shared.b16 {%0,%1,%2,%3}, [%4];" \
        : "=r"((r)[0]), "=r"((r)[1]), "=r"((r)[2]), "=r"((r)[3]) : "r"(addr))

#define MMA_F16(c, a, b) \
    asm volatile("mma.sync.aligned.m16n8k16.row.col.f32.f16.f16.f32 " \
        "{%0,%1,%2,%3}, {%4,%5,%6,%7}, {%8,%9}, {%0,%1,%2,%3};" \
        : "+f"((c)[0]), "+f"((c)[1]), "+f"((c)[2]), "+f"((c)[3]) \
        : "r"((a)[0]), "r"((a)[1]), "r"((a)[2]), "r"((a)[3]), "r"((b)[0]), "r"((b)[1]))

// smem: padded rows of 136 half = 272 B (17x16B -> conflict-free ldmatrix)
#define ROWB 272
#define SA    0
#define SB_HI (SA + 128 * ROWB)
#define SB_LO (SB_HI + 128 * ROWB)
#define SM_TOTAL (SB_LO + 128 * ROWB)   // 104448 B -> 2 CTAs/SM

// ---------------- 0) prep: W[k][n] -> fp16 hi/lo B[n][k] images ----------------
__global__ void prepB_kernel(const float* __restrict__ W) {
    int idx = blockIdx.x * blockDim.x + threadIdx.x;
    if (idx >= 16384) return;
    int k = idx >> 7, n = idx & 127;
    float x = W[idx];
    __half hi = __float2half_rn(x);
    __half lo = __float2half_rn(x - __half2float(hi));
    ((__half*)g_Bhi4)[n * 128 + k] = hi;
    ((__half*)g_Blo4)[n * 128 + k] = lo;
}

// ---------------- 1) mma.sync 2-term fp16 GEMM + fused fp16-ft / el / er --------
__global__ __launch_bounds__(256, 2) void gemm_mma_kernel(const float* __restrict__ A,
                                                          const float* __restrict__ attn_l,
                                                          const float* __restrict__ attn_r,
                                                          int M) {
    extern __shared__ char smem[];
    const uint32_t sb = smem_u32(smem);
    const int tid = threadIdx.x, wid = tid >> 5, lane = tid & 31;
    const int bm = blockIdx.x * 128;

    // stage B hi/lo: 2048 uint4 per image, 16 uint4 (256B) per packed row
    for (int i = tid; i < 2048; i += 256) {
        int row = i >> 4, c = i & 15;
        *(uint4*)(smem + SB_HI + row * ROWB + c * 16) = g_Bhi4[i];
        *(uint4*)(smem + SB_LO + row * ROWB + c * 16) = g_Blo4[i];
    }
    // stage A: fp32 -> fp16 (single term)
#pragma unroll 4
    for (int it = 0; it < 16; it++) {
        int idx = tid + it * 256;            // 0..4095 (128 rows x 32 float4)
        int row = idx >> 5, c4 = (idx & 31) * 4;
        float4 v = make_float4(0.f, 0.f, 0.f, 0.f);
        if (bm + row < M) v = *(const float4*)(A + (size_t)(bm + row) * 128 + c4);
        __half2 hA = __floats2half2_rn(v.x, v.y);
        __half2 hB = __floats2half2_rn(v.z, v.w);
        *(uint2*)(smem + SA + row * ROWB + c4 * 2) = make_uint2(*(uint32_t*)&hA, *(uint32_t*)&hB);
    }
    __syncthreads();

    const int wm = wid & 3, wn = wid >> 2;
    const int m0 = wm * 32, n0 = wn * 64;

    float acc[2][8][4];
#pragma unroll
    for (int i = 0; i < 2; i++)
#pragma unroll
        for (int j = 0; j < 8; j++)
#pragma unroll
            for (int q = 0; q < 4; q++) acc[i][j][q] = 0.f;

    // ldmatrix per-lane base addresses
    const uint32_t a_row = m0 + (lane & 15);
    const uint32_t a_off = a_row * ROWB + ((lane >> 4) << 4);
    const uint32_t b_row = n0 + (lane & 7) + ((lane >> 4) << 3);
    const uint32_t b_off = b_row * ROWB + (((lane >> 3) & 1) << 4);
    const uint32_t a_b  = sb + SA + a_off;
    const uint32_t bh_b = sb + SB_HI + b_off, bl_b = sb + SB_LO + b_off;

#pragma unroll
    for (int ks = 0; ks < 8; ks++) {
        const uint32_t k0b = ks * 32;   // 16 cols * 2B
        uint32_t av[2][4], bh[8][2], bl[8][2];
        LDM4(av[0], a_b + k0b);
        LDM4(av[1], a_b + 16 * ROWB + k0b);
#pragma unroll
        for (int jj = 0; jj < 4; jj++) {
            uint32_t r[4];
            LDM4(r, bh_b + jj * 16 * ROWB + k0b);
            bh[2 * jj][0] = r[0]; bh[2 * jj][1] = r[1];
            bh[2 * jj + 1][0] = r[2]; bh[2 * jj + 1][1] = r[3];
            LDM4(r, bl_b + jj * 16 * ROWB + k0b);
            bl[2 * jj][0] = r[0]; bl[2 * jj][1] = r[1];
            bl[2 * jj + 1][0] = r[2]; bl[2 * jj + 1][1] = r[3];
        }
#pragma unroll
        for (int im = 0; im < 2; im++)
#pragma unroll
            for (int jn = 0; jn < 8; jn++) {
                MMA_F16(acc[im][jn], av[im], bh[jn]);   // A * B_hi
                MMA_F16(acc[im][jn], av[im], bl[jn]);   // A * B_lo
            }
    }

    // epilogue: fp16 ft + exact el/er (quad owns full 32-col head dot)
    // attn vectors pre-scaled by LOG2E so agg can use bare ex2.
    float alv[16], arv[16];
#pragma unroll
    for (int j = 0; j < 8; j++) {
        int c0 = n0 + j * 8 + 2 * (lane & 3);
        alv[2 * j] = __ldg(attn_l + c0) * LOG2E; alv[2 * j + 1] = __ldg(attn_l + c0 + 1) * LOG2E;
        arv[2 * j] = __ldg(attn_r + c0) * LOG2E; arv[2 * j + 1] = __ldg(attn_r + c0 + 1) * LOG2E;
    }
    const int hA = n0 >> 5;            // heads hA, hA+1
#pragma unroll
    for (int im = 0; im < 2; im++) {
#pragma unroll
        for (int hf = 0; hf < 2; hf++) {
            int row = bm + m0 + im * 16 + (lane >> 2) + hf * 8;
            float sA = 0.f, sB = 0.f, rA = 0.f, rB = 0.f;
            uint32_t pk[8];
#pragma unroll
            for (int j = 0; j < 8; j++) {
                float v0 = acc[im][j][hf * 2], v1 = acc[im][j][hf * 2 + 1];
                __half2 hh = __floats2half2_rn(v0, v1);
                pk[j] = *(uint32_t*)&hh;
                if (j < 4) {
                    sA = fmaf(v0, alv[2 * j], fmaf(v1, alv[2 * j + 1], sA));
                    rA = fmaf(v0, arv[2 * j], fmaf(v1, arv[2 * j + 1], rA));
                } else {
                    sB = fmaf(v0, alv[2 * j], fmaf(v1, alv[2 * j + 1], sB));
                    rB = fmaf(v0, arv[2 * j], fmaf(v1, arv[2 * j + 1], rB));
                }
            }
            if (row < M) {
                uint32_t* dst = g_fth + (size_t)row * 64 + (n0 >> 1) + (lane & 3);
#pragma unroll
                for (int j = 0; j < 8; j++) dst[j * 4] = pk[j];
            }
            sA += __shfl_xor_sync(~0u, sA, 1); sA += __shfl_xor_sync(~0u, sA, 2);
            sB += __shfl_xor_sync(~0u, sB, 1); sB += __shfl_xor_sync(~0u, sB, 2);
            rA += __shfl_xor_sync(~0u, rA, 1); rA += __shfl_xor_sync(~0u, rA, 2);
            rB += __shfl_xor_sync(~0u, rB, 1); rB += __shfl_xor_sync(~0u, rB, 2);
            if ((lane & 3) == 0 && row < M) {
                g_el[row * 4 + hA]     = sA;
                g_el[row * 4 + hA + 1] = sB;
                g_er[row * 4 + hA]     = rA;
                g_er[row * 4 + hA + 1] = rB;
            }
        }
    }
}

// ---------------- 2) CSR offsets from sorted dst (binary search) ----------------
__global__ void offs_kernel(const int* __restrict__ dst, int N, int E) {
    int n = blockIdx.x * blockDim.x + threadIdx.x;
    if (n > N) return;
    int lo = 0, hi = E;
    while (lo < hi) {
        int mid = (lo + hi) >> 1;
        if (__ldg(dst + mid) < n) lo = mid + 1; else hi = mid;
    }
    g_offs[n] = lo;
}

// ---------------- 3) aggregation: 1 warp/node, half-warp per edge, FFMA2 -------
// 16 lanes per edge (lane slice = 8 feats via one LDG.128); scores use bare ex2
// (el/er pre-scaled by LOG2E); accumulation via packed fma.rn.f32x2.
__global__ __launch_bounds__(256) void agg_kernel(const int* __restrict__ src,
                                                  float* __restrict__ out, int N) {
    int gid  = blockIdx.x * blockDim.x + threadIdx.x;
    int node = gid >> 5;
    int lane = gid & 31;
    if (node >= N) return;

    const int half = lane >> 4;       // 0/1: which edge of the pair
    const int sl   = lane & 15;       // feature slice: halves [8*sl, 8*sl+8)
    const int h    = sl >> 2;         // head of this slice

    int s = g_offs[node];
    int e = g_offs[node + 1];
    float er_h = g_er[node * 4 + h];

    float psum = 0.f;
    unsigned long long acc[4];
#pragma unroll
    for (int q = 0; q < 4; q++) acc[q] = 0ull;

    const uint4* ft = (const uint4*)g_fth;   // 16 uint4 per row
#pragma unroll 2
    for (int i = s + half; i < e; i += 2) {
        int sn = __ldg(src + i);
        float sc = __ldg(&g_el[sn * 4 + h]) + er_h;   // already in log2 domain
        sc = fmaxf(sc, NEG_SLOPE * sc);               // leaky commutes with +scale
        float p;
        asm("ex2.approx.f32 %0, %1;" : "=f"(p) : "f"(sc));
        psum += p;
        unsigned long long pp;
        asm("mov.b64 %0, {%1, %1};" : "=l"(pp) : "r"(__float_as_uint(p)));
        uint4 v = __ldg(&ft[(size_t)sn * 16 + sl]);
        const __half2* hv = (const __half2*)&v;
#pragma unroll
        for (int q = 0; q < 4; q++) {
            float2 f = __half22float2(hv[q]);
            unsigned long long ff;
            asm("mov.b64 %0, {%1, %2};" : "=l"(ff)
                : "r"(__float_as_uint(f.x)), "r"(__float_as_uint(f.y)));
            asm("fma.rn.f32x2 %0, %1, %2, %0;" : "+l"(acc[q]) : "l"(pp), "l"(ff));
        }
    }

    // combine the two half-warps
    psum += __shfl_xor_sync(~0u, psum, 16);
    float a[8];
#pragma unroll
    for (int q = 0; q < 4; q++) {
        uint32_t lo, hi;
        asm("mov.b64 {%0, %1}, %2;" : "=r"(lo), "=r"(hi) : "l"(acc[q]));
        a[2 * q]     = __uint_as_float(lo);
        a[2 * q + 1] = __uint_as_float(hi);
    }
#pragma unroll
    for (int q = 0; q < 8; q++) a[q] += __shfl_xor_sync(~0u, a[q], 16);

    if (half == 0) {
        float inv = (psum > 0.f) ? (1.f / psum) : 0.f;
        float* dst = out + (size_t)node * 128 + sl * 8;
        *(float4*)dst       = make_float4(a[0] * inv, a[1] * inv, a[2] * inv, a[3] * inv);
        *(float4*)(dst + 4) = make_float4(a[4] * inv, a[5] * inv, a[6] * inv, a[7] * inv);
    }
}

// ---------------- launch ----------------
extern "C" void kernel_launch(void* const* d_in, const int* in_sizes, int n_in,
                              void* d_out, int out_size) {
    const float* feat   = (const float*)d_in[0];
    const int*   src    = (const int*)d_in[1];
    const int*   dst    = (const int*)d_in[2];
    const float* W      = (const float*)d_in[3];
    const float* attn_l = (const float*)d_in[4];
    const float* attn_r = (const float*)d_in[5];
    float* out = (float*)d_out;

    int M = in_sizes[0] / 128;   // nodes
    int E = in_sizes[1];         // edges

    cudaFuncSetAttribute(gemm_mma_kernel, cudaFuncAttributeMaxDynamicSharedMemorySize, SM_TOTAL);

    prepB_kernel<<<64, 256>>>(W);
    offs_kernel<<<(M + 1 + 255) / 256, 256>>>(dst, M, E);
    gemm_mma_kernel<<<(M + 127) / 128, 256, SM_TOTAL>>>(feat, attn_l, attn_r, M);
    agg_kernel<<<((size_t)M * 32 + 255) / 256, 256>>>(src, out, M);
}

// round 11
// speedup vs baseline: 1.3215x; 1.0738x over previous
#include <cuda_runtime.h>
#include <cuda_bf16.h>
#include <cuda_fp16.h>
#include <math.h>
#include <stdint.h>

#define N_NODES_MAX 100000
#define NEG_SLOPE 0.2f
#define LOG2E 1.4426950408889634f

// ---------------- scratch (device globals: alloc-free) ----------------
__device__ float    g_el[N_NODES_MAX * 4];    // pre-scaled by LOG2E
__device__ float    g_er[N_NODES_MAX * 4];    // pre-scaled by LOG2E
__device__ int      g_offs[N_NODES_MAX + 1];
__device__ uint32_t g_fth[N_NODES_MAX * 64];  // fp16 ft rows: 64 uint32 = 128 half
__device__ uint4    g_Bh4[2048];              // fp16 B[n][k] image (128x128 = 32KB)

__device__ __forceinline__ uint32_t smem_u32(const void* p) {
    uint32_t a;
    asm("{ .reg .u64 t; cvta.to.shared.u64 t, %1; cvt.u32.u64 %0, t; }" : "=r"(a) : "l"(p));
    return a;
}

#define LDM4(r, addr) \
    asm volatile("ldmatrix.sync.aligned.m8n8.x4.shared.b16 {%0,%1,%2,%3}, [%4];" \
        : "=r"((r)[0]), "=r"((r)[1]), "=r"((r)[2]), "=r"((r)[3]) : "r"(addr))

#define MMA_F16(c, a, b) \
    asm volatile("mma.sync.aligned.m16n8k16.row.col.f32.f16.f16.f32 " \
        "{%0,%1,%2,%3}, {%4,%5,%6,%7}, {%8,%9}, {%0,%1,%2,%3};" \
        : "+f"((c)[0]), "+f"((c)[1]), "+f"((c)[2]), "+f"((c)[3]) \
        : "r"((a)[0]), "r"((a)[1]), "r"((a)[2]), "r"((a)[3]), "r"((b)[0]), "r"((b)[1]))

// smem: padded rows of 136 half = 272 B (17x16B -> conflict-free ldmatrix)
#define ROWB 272
#define SA    0
#define SB    (SA + 128 * ROWB)
#define SM_TOTAL (SB + 128 * ROWB)   // 69632 B -> 2 CTAs/SM (smem would allow 3)

// ---------------- 0) prep: W[k][n] -> fp16 B[n][k] image -----------------------
__global__ void prepB_kernel(const float* __restrict__ W) {
    int idx = blockIdx.x * blockDim.x + threadIdx.x;
    if (idx >= 16384) return;
    int k = idx >> 7, n = idx & 127;
    ((__half*)g_Bh4)[n * 128 + k] = __float2half_rn(W[idx]);
}

// ---------------- 1) mma.sync single-term fp16 GEMM + fused ft / el / er -------
__global__ __launch_bounds__(256, 2) void gemm_mma_kernel(const float* __restrict__ A,
                                                          const float* __restrict__ attn_l,
                                                          const float* __restrict__ attn_r,
                                                          int M) {
    extern __shared__ char smem[];
    const uint32_t sb = smem_u32(smem);
    const int tid = threadIdx.x, wid = tid >> 5, lane = tid & 31;
    const int bm = blockIdx.x * 128;

    // stage B: 2048 uint4, 16 uint4 (256B) per packed row -> 272B padded rows
    for (int i = tid; i < 2048; i += 256) {
        int row = i >> 4, c = i & 15;
        *(uint4*)(smem + SB + row * ROWB + c * 16) = g_Bh4[i];
    }
    // stage A: fp32 -> fp16
#pragma unroll 4
    for (int it = 0; it < 16; it++) {
        int idx = tid + it * 256;            // 0..4095 (128 rows x 32 float4)
        int row = idx >> 5, c4 = (idx & 31) * 4;
        float4 v = make_float4(0.f, 0.f, 0.f, 0.f);
        if (bm + row < M) v = *(const float4*)(A + (size_t)(bm + row) * 128 + c4);
        __half2 hA = __floats2half2_rn(v.x, v.y);
        __half2 hB = __floats2half2_rn(v.z, v.w);
        *(uint2*)(smem + SA + row * ROWB + c4 * 2) = make_uint2(*(uint32_t*)&hA, *(uint32_t*)&hB);
    }
    __syncthreads();

    const int wm = wid & 3, wn = wid >> 2;
    const int m0 = wm * 32, n0 = wn * 64;

    float acc[2][8][4];
#pragma unroll
    for (int i = 0; i < 2; i++)
#pragma unroll
        for (int j = 0; j < 8; j++)
#pragma unroll
            for (int q = 0; q < 4; q++) acc[i][j][q] = 0.f;

    // ldmatrix per-lane base addresses
    const uint32_t a_row = m0 + (lane & 15);
    const uint32_t a_off = a_row * ROWB + ((lane >> 4) << 4);
    const uint32_t b_row = n0 + (lane & 7) + ((lane >> 4) << 3);
    const uint32_t b_off = b_row * ROWB + (((lane >> 3) & 1) << 4);
    const uint32_t a_b = sb + SA + a_off;
    const uint32_t b_b = sb + SB + b_off;

#pragma unroll
    for (int ks = 0; ks < 8; ks++) {
        const uint32_t k0b = ks * 32;   // 16 cols * 2B
        uint32_t av[2][4], bh[8][2];
        LDM4(av[0], a_b + k0b);
        LDM4(av[1], a_b + 16 * ROWB + k0b);
#pragma unroll
        for (int jj = 0; jj < 4; jj++) {
            uint32_t r[4];
            LDM4(r, b_b + jj * 16 * ROWB + k0b);
            bh[2 * jj][0] = r[0]; bh[2 * jj][1] = r[1];
            bh[2 * jj + 1][0] = r[2]; bh[2 * jj + 1][1] = r[3];
        }
#pragma unroll
        for (int im = 0; im < 2; im++)
#pragma unroll
            for (int jn = 0; jn < 8; jn++)
                MMA_F16(acc[im][jn], av[im], bh[jn]);
    }

    // epilogue: fp16 ft + exact el/er (quad owns full 32-col head dot)
    // attn vectors pre-scaled by LOG2E so agg can use bare ex2.
    float alv[16], arv[16];
#pragma unroll
    for (int j = 0; j < 8; j++) {
        int c0 = n0 + j * 8 + 2 * (lane & 3);
        alv[2 * j] = __ldg(attn_l + c0) * LOG2E; alv[2 * j + 1] = __ldg(attn_l + c0 + 1) * LOG2E;
        arv[2 * j] = __ldg(attn_r + c0) * LOG2E; arv[2 * j + 1] = __ldg(attn_r + c0 + 1) * LOG2E;
    }
    const int hA = n0 >> 5;            // heads hA, hA+1
#pragma unroll
    for (int im = 0; im < 2; im++) {
#pragma unroll
        for (int hf = 0; hf < 2; hf++) {
            int row = bm + m0 + im * 16 + (lane >> 2) + hf * 8;
            float sA = 0.f, sB = 0.f, rA = 0.f, rB = 0.f;
            uint32_t pk[8];
#pragma unroll
            for (int j = 0; j < 8; j++) {
                float v0 = acc[im][j][hf * 2], v1 = acc[im][j][hf * 2 + 1];
                __half2 hh = __floats2half2_rn(v0, v1);
                pk[j] = *(uint32_t*)&hh;
                if (j < 4) {
                    sA = fmaf(v0, alv[2 * j], fmaf(v1, alv[2 * j + 1], sA));
                    rA = fmaf(v0, arv[2 * j], fmaf(v1, arv[2 * j + 1], rA));
                } else {
                    sB = fmaf(v0, alv[2 * j], fmaf(v1, alv[2 * j + 1], sB));
                    rB = fmaf(v0, arv[2 * j], fmaf(v1, arv[2 * j + 1], rB));
                }
            }
            if (row < M) {
                uint32_t* dst = g_fth + (size_t)row * 64 + (n0 >> 1) + (lane & 3);
#pragma unroll
                for (int j = 0; j < 8; j++) dst[j * 4] = pk[j];
            }
            sA += __shfl_xor_sync(~0u, sA, 1); sA += __shfl_xor_sync(~0u, sA, 2);
            sB += __shfl_xor_sync(~0u, sB, 1); sB += __shfl_xor_sync(~0u, sB, 2);
            rA += __shfl_xor_sync(~0u, rA, 1); rA += __shfl_xor_sync(~0u, rA, 2);
            rB += __shfl_xor_sync(~0u, rB, 1); rB += __shfl_xor_sync(~0u, rB, 2);
            if ((lane & 3) == 0 && row < M) {
                g_el[row * 4 + hA]     = sA;
                g_el[row * 4 + hA + 1] = sB;
                g_er[row * 4 + hA]     = rA;
                g_er[row * 4 + hA + 1] = rB;
            }
        }
    }
}

// ---------------- 2) CSR offsets from sorted dst (binary search) ----------------
__global__ void offs_kernel(const int* __restrict__ dst, int N, int E) {
    int n = blockIdx.x * blockDim.x + threadIdx.x;
    if (n > N) return;
    int lo = 0, hi = E;
    while (lo < hi) {
        int mid = (lo + hi) >> 1;
        if (__ldg(dst + mid) < n) lo = mid + 1; else hi = mid;
    }
    g_offs[n] = lo;
}

// ---------------- 3) aggregation: 1 warp/node, half-warp per edge, FFMA2 -------
// (identical to round-10 passing version)
__global__ __launch_bounds__(256) void agg_kernel(const int* __restrict__ src,
                                                  float* __restrict__ out, int N) {
    int gid  = blockIdx.x * blockDim.x + threadIdx.x;
    int node = gid >> 5;
    int lane = gid & 31;
    if (node >= N) return;

    const int half = lane >> 4;       // 0/1: which edge of the pair
    const int sl   = lane & 15;       // feature slice: halves [8*sl, 8*sl+8)
    const int h    = sl >> 2;         // head of this slice

    int s = g_offs[node];
    int e = g_offs[node + 1];
    float er_h = g_er[node * 4 + h];

    float psum = 0.f;
    unsigned long long acc[4];
#pragma unroll
    for (int q = 0; q < 4; q++) acc[q] = 0ull;

    const uint4* ft = (const uint4*)g_fth;   // 16 uint4 per row
#pragma unroll 2
    for (int i = s + half; i < e; i += 2) {
        int sn = __ldg(src + i);
        float sc = __ldg(&g_el[sn * 4 + h]) + er_h;   // already in log2 domain
        sc = fmaxf(sc, NEG_SLOPE * sc);               // leaky commutes with +scale
        float p;
        asm("ex2.approx.f32 %0, %1;" : "=f"(p) : "f"(sc));
        psum += p;
        unsigned long long pp;
        asm("mov.b64 %0, {%1, %1};" : "=l"(pp) : "r"(__float_as_uint(p)));
        uint4 v = __ldg(&ft[(size_t)sn * 16 + sl]);
        const __half2* hv = (const __half2*)&v;
#pragma unroll
        for (int q = 0; q < 4; q++) {
            float2 f = __half22float2(hv[q]);
            unsigned long long ff;
            asm("mov.b64 %0, {%1, %2};" : "=l"(ff)
                : "r"(__float_as_uint(f.x)), "r"(__float_as_uint(f.y)));
            asm("fma.rn.f32x2 %0, %1, %2, %0;" : "+l"(acc[q]) : "l"(pp), "l"(ff));
        }
    }

    // combine the two half-warps
    psum += __shfl_xor_sync(~0u, psum, 16);
    float a[8];
#pragma unroll
    for (int q = 0; q < 4; q++) {
        uint32_t lo, hi;
        asm("mov.b64 {%0, %1}, %2;" : "=r"(lo), "=r"(hi) : "l"(acc[q]));
        a[2 * q]     = __uint_as_float(lo);
        a[2 * q + 1] = __uint_as_float(hi);
    }
#pragma unroll
    for (int q = 0; q < 8; q++) a[q] += __shfl_xor_sync(~0u, a[q], 16);

    if (half == 0) {
        float inv = (psum > 0.f) ? (1.f / psum) : 0.f;
        float* dst = out + (size_t)node * 128 + sl * 8;
        *(float4*)dst       = make_float4(a[0] * inv, a[1] * inv, a[2] * inv, a[3] * inv);
        *(float4*)(dst + 4) = make_float4(a[4] * inv, a[5] * inv, a[6] * inv, a[7] * inv);
    }
}

// ---------------- launch ----------------
extern "C" void kernel_launch(void* const* d_in, const int* in_sizes, int n_in,
                              void* d_out, int out_size) {
    const float* feat   = (const float*)d_in[0];
    const int*   src    = (const int*)d_in[1];
    const int*   dst    = (const int*)d_in[2];
    const float* W      = (const float*)d_in[3];
    const float* attn_l = (const float*)d_in[4];
    const float* attn_r = (const float*)d_in[5];
    float* out = (float*)d_out;

    int M = in_sizes[0] / 128;   // nodes
    int E = in_sizes[1];         // edges

    cudaFuncSetAttribute(gemm_mma_kernel, cudaFuncAttributeMaxDynamicSharedMemorySize, SM_TOTAL);

    prepB_kernel<<<64, 256>>>(W);
    offs_kernel<<<(M + 1 + 255) / 256, 256>>>(dst, M, E);
    gemm_mma_kernel<<<(M + 127) / 128, 256, SM_TOTAL>>>(feat, attn_l, attn_r, M);
    agg_kernel<<<((size_t)M * 32 + 255) / 256, 256>>>(src, out, M);
}

// round 12
// speedup vs baseline: 1.4762x; 1.1171x over previous
#include <cuda_runtime.h>
#include <cuda_bf16.h>
#include <cuda_fp16.h>
#include <math.h>
#include <stdint.h>

#define N_NODES_MAX 100000
#define NEG_SLOPE 0.2f
#define LOG2E 1.4426950408889634f

// ---------------- scratch (device globals: alloc-free) ----------------
__device__ float    g_el[N_NODES_MAX * 4];    // pre-scaled by LOG2E
__device__ float    g_er[N_NODES_MAX * 4];    // pre-scaled by LOG2E
__device__ int      g_offs[N_NODES_MAX + 1];
__device__ uint32_t g_fth[N_NODES_MAX * 64];  // fp16 ft rows: 64 uint32 = 128 half
__device__ uint4    g_Bh4[2048];              // fp16 B[n][k] image (128x128 = 32KB)

__device__ __forceinline__ uint32_t smem_u32(const void* p) {
    uint32_t a;
    asm("{ .reg .u64 t; cvta.to.shared.u64 t, %1; cvt.u32.u64 %0, t; }" : "=r"(a) : "l"(p));
    return a;
}

#define LDM4(r, addr) \
    asm volatile("ldmatrix.sync.aligned.m8n8.x4.shared.b16 {%0,%1,%2,%3}, [%4];" \
        : "=r"((r)[0]), "=r"((r)[1]), "=r"((r)[2]), "=r"((r)[3]) : "r"(addr))

#define MMA_F16(c, a, b) \
    asm volatile("mma.sync.aligned.m16n8k16.row.col.f32.f16.f16.f32 " \
        "{%0,%1,%2,%3}, {%4,%5,%6,%7}, {%8,%9}, {%0,%1,%2,%3};" \
        : "+f"((c)[0]), "+f"((c)[1]), "+f"((c)[2]), "+f"((c)[3]) \
        : "r"((a)[0]), "r"((a)[1]), "r"((a)[2]), "r"((a)[3]), "r"((b)[0]), "r"((b)[1]))

// smem: padded rows of 136 half = 272 B (17x16B -> conflict-free ldmatrix)
#define ROWB 272
#define SA    0
#define SB    (SA + 128 * ROWB)
#define SM_TOTAL (SB + 128 * ROWB)   // 69632 B -> 2 CTAs/SM

// ------- 0) prep: W -> fp16 B image (blocks 0..63) + CSR offsets (blocks 64..) --
__global__ void prep_kernel(const float* __restrict__ W,
                            const int* __restrict__ dst, int N, int E) {
    int b = blockIdx.x;
    if (b < 64) {
        int idx = b * 256 + threadIdx.x;        // 0..16383
        int k = idx >> 7, n = idx & 127;
        ((__half*)g_Bh4)[n * 128 + k] = __float2half_rn(W[idx]);
    } else {
        int n = (b - 64) * 256 + threadIdx.x;
        if (n > N) return;
        int lo = 0, hi = E;
        while (lo < hi) {
            int mid = (lo + hi) >> 1;
            if (__ldg(dst + mid) < n) lo = mid + 1; else hi = mid;
        }
        g_offs[n] = lo;
    }
}

// ---------------- 1) mma.sync single-term fp16 GEMM + fused ft / el / er -------
__global__ __launch_bounds__(256, 2) void gemm_mma_kernel(const float* __restrict__ A,
                                                          const float* __restrict__ attn_l,
                                                          const float* __restrict__ attn_r,
                                                          int M) {
    extern __shared__ char smem[];
    const uint32_t sb = smem_u32(smem);
    const int tid = threadIdx.x, wid = tid >> 5, lane = tid & 31;
    const int bm = blockIdx.x * 128;
    const bool full = (bm + 128 <= M);

    if (full) {
        // fast path: batch loads for MLP (8 B-LDGs + 8 A-LDGs in flight), no predicates
        uint4 bv[8];
#pragma unroll
        for (int i = 0; i < 8; i++) bv[i] = g_Bh4[tid + i * 256];
        float4 av4[8];
#pragma unroll
        for (int it = 0; it < 8; it++) {
            int idx = tid + it * 256;
            av4[it] = *(const float4*)(A + (size_t)(bm + (idx >> 5)) * 128 + (idx & 31) * 4);
        }
#pragma unroll
        for (int i = 0; i < 8; i++) {
            int t = tid + i * 256;
            *(uint4*)(smem + SB + (t >> 4) * ROWB + (t & 15) * 16) = bv[i];
        }
#pragma unroll
        for (int it = 0; it < 8; it++) {
            int idx = tid + it * 256;
            __half2 hA = __floats2half2_rn(av4[it].x, av4[it].y);
            __half2 hB = __floats2half2_rn(av4[it].z, av4[it].w);
            *(uint2*)(smem + SA + (idx >> 5) * ROWB + (idx & 31) * 8) =
                make_uint2(*(uint32_t*)&hA, *(uint32_t*)&hB);
        }
#pragma unroll
        for (int it = 8; it < 16; it++) {
            int idx = tid + it * 256;
            float4 v = *(const float4*)(A + (size_t)(bm + (idx >> 5)) * 128 + (idx & 31) * 4);
            __half2 hA = __floats2half2_rn(v.x, v.y);
            __half2 hB = __floats2half2_rn(v.z, v.w);
            *(uint2*)(smem + SA + (idx >> 5) * ROWB + (idx & 31) * 8) =
                make_uint2(*(uint32_t*)&hA, *(uint32_t*)&hB);
        }
    } else {
        for (int i = tid; i < 2048; i += 256) {
            int row = i >> 4, c = i & 15;
            *(uint4*)(smem + SB + row * ROWB + c * 16) = g_Bh4[i];
        }
#pragma unroll 4
        for (int it = 0; it < 16; it++) {
            int idx = tid + it * 256;
            int row = idx >> 5, c4 = (idx & 31) * 4;
            float4 v = make_float4(0.f, 0.f, 0.f, 0.f);
            if (bm + row < M) v = *(const float4*)(A + (size_t)(bm + row) * 128 + c4);
            __half2 hA = __floats2half2_rn(v.x, v.y);
            __half2 hB = __floats2half2_rn(v.z, v.w);
            *(uint2*)(smem + SA + row * ROWB + c4 * 2) = make_uint2(*(uint32_t*)&hA, *(uint32_t*)&hB);
        }
    }
    __syncthreads();

    const int wm = wid & 3, wn = wid >> 2;
    const int m0 = wm * 32, n0 = wn * 64;

    float acc[2][8][4];
#pragma unroll
    for (int i = 0; i < 2; i++)
#pragma unroll
        for (int j = 0; j < 8; j++)
#pragma unroll
            for (int q = 0; q < 4; q++) acc[i][j][q] = 0.f;

    // ldmatrix per-lane base addresses
    const uint32_t a_row = m0 + (lane & 15);
    const uint32_t a_off = a_row * ROWB + ((lane >> 4) << 4);
    const uint32_t b_row = n0 + (lane & 7) + ((lane >> 4) << 3);
    const uint32_t b_off = b_row * ROWB + (((lane >> 3) & 1) << 4);
    const uint32_t a_b = sb + SA + a_off;
    const uint32_t b_b = sb + SB + b_off;

#pragma unroll
    for (int ks = 0; ks < 8; ks++) {
        const uint32_t k0b = ks * 32;   // 16 cols * 2B
        uint32_t av[2][4], bh[8][2];
        LDM4(av[0], a_b + k0b);
        LDM4(av[1], a_b + 16 * ROWB + k0b);
#pragma unroll
        for (int jj = 0; jj < 4; jj++) {
            uint32_t r[4];
            LDM4(r, b_b + jj * 16 * ROWB + k0b);
            bh[2 * jj][0] = r[0]; bh[2 * jj][1] = r[1];
            bh[2 * jj + 1][0] = r[2]; bh[2 * jj + 1][1] = r[3];
        }
#pragma unroll
        for (int im = 0; im < 2; im++)
#pragma unroll
            for (int jn = 0; jn < 8; jn++)
                MMA_F16(acc[im][jn], av[im], bh[jn]);
    }

    // epilogue: fp16 ft + exact el/er (quad owns full 32-col head dot)
    // attn vectors pre-scaled by LOG2E so agg can use bare ex2.
    float alv[16], arv[16];
#pragma unroll
    for (int j = 0; j < 8; j++) {
        int c0 = n0 + j * 8 + 2 * (lane & 3);
        alv[2 * j] = __ldg(attn_l + c0) * LOG2E; alv[2 * j + 1] = __ldg(attn_l + c0 + 1) * LOG2E;
        arv[2 * j] = __ldg(attn_r + c0) * LOG2E; arv[2 * j + 1] = __ldg(attn_r + c0 + 1) * LOG2E;
    }
    const int hA = n0 >> 5;            // heads hA, hA+1
#pragma unroll
    for (int im = 0; im < 2; im++) {
#pragma unroll
        for (int hf = 0; hf < 2; hf++) {
            int row = bm + m0 + im * 16 + (lane >> 2) + hf * 8;
            float sA = 0.f, sB = 0.f, rA = 0.f, rB = 0.f;
            uint32_t pk[8];
#pragma unroll
            for (int j = 0; j < 8; j++) {
                float v0 = acc[im][j][hf * 2], v1 = acc[im][j][hf * 2 + 1];
                __half2 hh = __floats2half2_rn(v0, v1);
                pk[j] = *(uint32_t*)&hh;
                if (j < 4) {
                    sA = fmaf(v0, alv[2 * j], fmaf(v1, alv[2 * j + 1], sA));
                    rA = fmaf(v0, arv[2 * j], fmaf(v1, arv[2 * j + 1], rA));
                } else {
                    sB = fmaf(v0, alv[2 * j], fmaf(v1, alv[2 * j + 1], sB));
                    rB = fmaf(v0, arv[2 * j], fmaf(v1, arv[2 * j + 1], rB));
                }
            }
            if (row < M) {
                uint32_t* dst = g_fth + (size_t)row * 64 + (n0 >> 1) + (lane & 3);
#pragma unroll
                for (int j = 0; j < 8; j++) dst[j * 4] = pk[j];
            }
            sA += __shfl_xor_sync(~0u, sA, 1); sA += __shfl_xor_sync(~0u, sA, 2);
            sB += __shfl_xor_sync(~0u, sB, 1); sB += __shfl_xor_sync(~0u, sB, 2);
            rA += __shfl_xor_sync(~0u, rA, 1); rA += __shfl_xor_sync(~0u, rA, 2);
            rB += __shfl_xor_sync(~0u, rB, 1); rB += __shfl_xor_sync(~0u, rB, 2);
            if ((lane & 3) == 0 && row < M) {
                g_el[row * 4 + hA]     = sA;
                g_el[row * 4 + hA + 1] = sB;
                g_er[row * 4 + hA]     = rA;
                g_er[row * 4 + hA + 1] = rB;
            }
        }
    }
}

// ---------------- 2) aggregation: 1 warp/node, half-warp per edge, FFMA2 -------
// (identical to round-10/11 passing version)
__global__ __launch_bounds__(256) void agg_kernel(const int* __restrict__ src,
                                                  float* __restrict__ out, int N) {
    int gid  = blockIdx.x * blockDim.x + threadIdx.x;
    int node = gid >> 5;
    int lane = gid & 31;
    if (node >= N) return;

    const int half = lane >> 4;       // 0/1: which edge of the pair
    const int sl   = lane & 15;       // feature slice: halves [8*sl, 8*sl+8)
    const int h    = sl >> 2;         // head of this slice

    int s = g_offs[node];
    int e = g_offs[node + 1];
    float er_h = g_er[node * 4 + h];

    float psum = 0.f;
    unsigned long long acc[4];
#pragma unroll
    for (int q = 0; q < 4; q++) acc[q] = 0ull;

    const uint4* ft = (const uint4*)g_fth;   // 16 uint4 per row
#pragma unroll 2
    for (int i = s + half; i < e; i += 2) {
        int sn = __ldg(src + i);
        float sc = __ldg(&g_el[sn * 4 + h]) + er_h;   // already in log2 domain
        sc = fmaxf(sc, NEG_SLOPE * sc);               // leaky commutes with +scale
        float p;
        asm("ex2.approx.f32 %0, %1;" : "=f"(p) : "f"(sc));
        psum += p;
        unsigned long long pp;
        asm("mov.b64 %0, {%1, %1};" : "=l"(pp) : "r"(__float_as_uint(p)));
        uint4 v = __ldg(&ft[(size_t)sn * 16 + sl]);
        const __half2* hv = (const __half2*)&v;
#pragma unroll
        for (int q = 0; q < 4; q++) {
            float2 f = __half22float2(hv[q]);
            unsigned long long ff;
            asm("mov.b64 %0, {%1, %2};" : "=l"(ff)
                : "r"(__float_as_uint(f.x)), "r"(__float_as_uint(f.y)));
            asm("fma.rn.f32x2 %0, %1, %2, %0;" : "+l"(acc[q]) : "l"(pp), "l"(ff));
        }
    }

    // combine the two half-warps
    psum += __shfl_xor_sync(~0u, psum, 16);
    float a[8];
#pragma unroll
    for (int q = 0; q < 4; q++) {
        uint32_t lo, hi;
        asm("mov.b64 {%0, %1}, %2;" : "=r"(lo), "=r"(hi) : "l"(acc[q]));
        a[2 * q]     = __uint_as_float(lo);
        a[2 * q + 1] = __uint_as_float(hi);
    }
#pragma unroll
    for (int q = 0; q < 8; q++) a[q] += __shfl_xor_sync(~0u, a[q], 16);

    if (half == 0) {
        float inv = (psum > 0.f) ? (1.f / psum) : 0.f;
        float* dst = out + (size_t)node * 128 + sl * 8;
        *(float4*)dst       = make_float4(a[0] * inv, a[1] * inv, a[2] * inv, a[3] * inv);
        *(float4*)(dst + 4) = make_float4(a[4] * inv, a[5] * inv, a[6] * inv, a[7] * inv);
    }
}

// ---------------- launch ----------------
extern "C" void kernel_launch(void* const* d_in, const int* in_sizes, int n_in,
                              void* d_out, int out_size) {
    const float* feat   = (const float*)d_in[0];
    const int*   src    = (const int*)d_in[1];
    const int*   dst    = (const int*)d_in[2];
    const float* W      = (const float*)d_in[3];
    const float* attn_l = (const float*)d_in[4];
    const float* attn_r = (const float*)d_in[5];
    float* out = (float*)d_out;

    int M = in_sizes[0] / 128;   // nodes
    int E = in_sizes[1];         // edges

    cudaFuncSetAttribute(gemm_mma_kernel, cudaFuncAttributeMaxDynamicSharedMemorySize, SM_TOTAL);

    int offsBlocks = (M + 1 + 255) / 256;
    prep_kernel<<<64 + offsBlocks, 256>>>(W, dst, M, E);
    gemm_mma_kernel<<<(M + 127) / 128, 256, SM_TOTAL>>>(feat, attn_l, attn_r, M);
    agg_kernel<<<((size_t)M * 32 + 255) / 256, 256>>>(src, out, M);
}

// round 13
// speedup vs baseline: 1.5482x; 1.0487x over previous
#include <cuda_runtime.h>
#include <cuda_bf16.h>
#include <cuda_fp16.h>
#include <math.h>
#include <stdint.h>

#define N_NODES_MAX 100000
#define NEG_SLOPE 0.2f
#define LOG2E 1.4426950408889634f

// ---------------- scratch (device globals: alloc-free) ----------------
__device__ float    g_el[N_NODES_MAX * 4];    // pre-scaled by LOG2E
__device__ float    g_er[N_NODES_MAX * 4];    // pre-scaled by LOG2E
__device__ int      g_offs[N_NODES_MAX + 1];
__device__ uint32_t g_fth[N_NODES_MAX * 64];  // fp16 ft rows: 64 uint32 = 128 half
__device__ uint4    g_Bh4[2048];              // fp16 B[n][k] image (128x128 = 32KB)

__device__ __forceinline__ uint32_t smem_u32(const void* p) {
    uint32_t a;
    asm("{ .reg .u64 t; cvta.to.shared.u64 t, %1; cvt.u32.u64 %0, t; }" : "=r"(a) : "l"(p));
    return a;
}

#define LDM4(r, addr) \
    asm volatile("ldmatrix.sync.aligned.m8n8.x4.shared.b16 {%0,%1,%2,%3}, [%4];" \
        : "=r"((r)[0]), "=r"((r)[1]), "=r"((r)[2]), "=r"((r)[3]) : "r"(addr))

#define MMA_F16(c, a, b) \
    asm volatile("mma.sync.aligned.m16n8k16.row.col.f32.f16.f16.f32 " \
        "{%0,%1,%2,%3}, {%4,%5,%6,%7}, {%8,%9}, {%0,%1,%2,%3};" \
        : "+f"((c)[0]), "+f"((c)[1]), "+f"((c)[2]), "+f"((c)[3]) \
        : "r"((a)[0]), "r"((a)[1]), "r"((a)[2]), "r"((a)[3]), "r"((b)[0]), "r"((b)[1]))

// smem: padded rows of 136 half = 272 B (17x16B -> conflict-free ldmatrix)
#define ROWB 272
#define SA    0
#define SB    (SA + 128 * ROWB)
#define SM_TOTAL (SB + 128 * ROWB)   // 69632 B -> 2 CTAs/SM

// ------- 0) prep: W -> fp16 B image (blocks 0..63) + offsets scatter (64..) ----
// dst is sorted: offs[n] = first i with dst[i] >= n, found by boundary compare.
__global__ void prep_kernel(const float* __restrict__ W,
                            const int* __restrict__ dst, int N, int E) {
    int b = blockIdx.x;
    if (b < 64) {
        int idx = b * 256 + threadIdx.x;        // 0..16383
        int k = idx >> 7, n = idx & 127;
        ((__half*)g_Bh4)[n * 128 + k] = __float2half_rn(W[idx]);
        return;
    }
    int i = (b - 64) * 256 + threadIdx.x;       // edge index
    if (i >= E) return;
    int d1 = __ldg(dst + i);
    if (i == 0) {
        for (int n = 0; n <= d1; n++) g_offs[n] = 0;
    } else {
        int d0 = __ldg(dst + i - 1);
        for (int n = d0 + 1; n <= d1; n++) g_offs[n] = i;
    }
    if (i == E - 1) {
        for (int n = d1 + 1; n <= N; n++) g_offs[n] = E;
    }
}

// ---------------- 1) mma.sync single-term fp16 GEMM + fused ft / el / er -------
__global__ __launch_bounds__(256, 2) void gemm_mma_kernel(const float* __restrict__ A,
                                                          const float* __restrict__ attn_l,
                                                          const float* __restrict__ attn_r,
                                                          int M) {
    extern __shared__ char smem[];
    const uint32_t sb = smem_u32(smem);
    const int tid = threadIdx.x, wid = tid >> 5, lane = tid & 31;
    const int bm = blockIdx.x * 128;
    const bool full = (bm + 128 <= M);

    if (full) {
        // fast path: batch loads for MLP (8 B-LDGs + 8 A-LDGs in flight), no predicates
        uint4 bv[8];
#pragma unroll
        for (int i = 0; i < 8; i++) bv[i] = g_Bh4[tid + i * 256];
        float4 av4[8];
#pragma unroll
        for (int it = 0; it < 8; it++) {
            int idx = tid + it * 256;
            av4[it] = *(const float4*)(A + (size_t)(bm + (idx >> 5)) * 128 + (idx & 31) * 4);
        }
#pragma unroll
        for (int i = 0; i < 8; i++) {
            int t = tid + i * 256;
            *(uint4*)(smem + SB + (t >> 4) * ROWB + (t & 15) * 16) = bv[i];
        }
#pragma unroll
        for (int it = 0; it < 8; it++) {
            int idx = tid + it * 256;
            __half2 hA = __floats2half2_rn(av4[it].x, av4[it].y);
            __half2 hB = __floats2half2_rn(av4[it].z, av4[it].w);
            *(uint2*)(smem + SA + (idx >> 5) * ROWB + (idx & 31) * 8) =
                make_uint2(*(uint32_t*)&hA, *(uint32_t*)&hB);
        }
#pragma unroll
        for (int it = 8; it < 16; it++) {
            int idx = tid + it * 256;
            float4 v = *(const float4*)(A + (size_t)(bm + (idx >> 5)) * 128 + (idx & 31) * 4);
            __half2 hA = __floats2half2_rn(v.x, v.y);
            __half2 hB = __floats2half2_rn(v.z, v.w);
            *(uint2*)(smem + SA + (idx >> 5) * ROWB + (idx & 31) * 8) =
                make_uint2(*(uint32_t*)&hA, *(uint32_t*)&hB);
        }
    } else {
        for (int i = tid; i < 2048; i += 256) {
            int row = i >> 4, c = i & 15;
            *(uint4*)(smem + SB + row * ROWB + c * 16) = g_Bh4[i];
        }
#pragma unroll 4
        for (int it = 0; it < 16; it++) {
            int idx = tid + it * 256;
            int row = idx >> 5, c4 = (idx & 31) * 4;
            float4 v = make_float4(0.f, 0.f, 0.f, 0.f);
            if (bm + row < M) v = *(const float4*)(A + (size_t)(bm + row) * 128 + c4);
            __half2 hA = __floats2half2_rn(v.x, v.y);
            __half2 hB = __floats2half2_rn(v.z, v.w);
            *(uint2*)(smem + SA + row * ROWB + c4 * 2) = make_uint2(*(uint32_t*)&hA, *(uint32_t*)&hB);
        }
    }
    __syncthreads();

    const int wm = wid & 3, wn = wid >> 2;
    const int m0 = wm * 32, n0 = wn * 64;

    float acc[2][8][4];
#pragma unroll
    for (int i = 0; i < 2; i++)
#pragma unroll
        for (int j = 0; j < 8; j++)
#pragma unroll
            for (int q = 0; q < 4; q++) acc[i][j][q] = 0.f;

    // ldmatrix per-lane base addresses
    const uint32_t a_row = m0 + (lane & 15);
    const uint32_t a_off = a_row * ROWB + ((lane >> 4) << 4);
    const uint32_t b_row = n0 + (lane & 7) + ((lane >> 4) << 3);
    const uint32_t b_off = b_row * ROWB + (((lane >> 3) & 1) << 4);
    const uint32_t a_b = sb + SA + a_off;
    const uint32_t b_b = sb + SB + b_off;

#pragma unroll
    for (int ks = 0; ks < 8; ks++) {
        const uint32_t k0b = ks * 32;   // 16 cols * 2B
        uint32_t av[2][4], bh[8][2];
        LDM4(av[0], a_b + k0b);
        LDM4(av[1], a_b + 16 * ROWB + k0b);
#pragma unroll
        for (int jj = 0; jj < 4; jj++) {
            uint32_t r[4];
            LDM4(r, b_b + jj * 16 * ROWB + k0b);
            bh[2 * jj][0] = r[0]; bh[2 * jj][1] = r[1];
            bh[2 * jj + 1][0] = r[2]; bh[2 * jj + 1][1] = r[3];
        }
#pragma unroll
        for (int im = 0; im < 2; im++)
#pragma unroll
            for (int jn = 0; jn < 8; jn++)
                MMA_F16(acc[im][jn], av[im], bh[jn]);
    }

    // epilogue: fp16 ft + exact el/er (quad owns full 32-col head dot)
    // attn vectors pre-scaled by LOG2E so agg can use bare ex2.
    float alv[16], arv[16];
#pragma unroll
    for (int j = 0; j < 8; j++) {
        int c0 = n0 + j * 8 + 2 * (lane & 3);
        alv[2 * j] = __ldg(attn_l + c0) * LOG2E; alv[2 * j + 1] = __ldg(attn_l + c0 + 1) * LOG2E;
        arv[2 * j] = __ldg(attn_r + c0) * LOG2E; arv[2 * j + 1] = __ldg(attn_r + c0 + 1) * LOG2E;
    }
    const int hA = n0 >> 5;            // heads hA, hA+1
#pragma unroll
    for (int im = 0; im < 2; im++) {
#pragma unroll
        for (int hf = 0; hf < 2; hf++) {
            int row = bm + m0 + im * 16 + (lane >> 2) + hf * 8;
            float sA = 0.f, sB = 0.f, rA = 0.f, rB = 0.f;
            uint32_t pk[8];
#pragma unroll
            for (int j = 0; j < 8; j++) {
                float v0 = acc[im][j][hf * 2], v1 = acc[im][j][hf * 2 + 1];
                __half2 hh = __floats2half2_rn(v0, v1);
                pk[j] = *(uint32_t*)&hh;
                if (j < 4) {
                    sA = fmaf(v0, alv[2 * j], fmaf(v1, alv[2 * j + 1], sA));
                    rA = fmaf(v0, arv[2 * j], fmaf(v1, arv[2 * j + 1], rA));
                } else {
                    sB = fmaf(v0, alv[2 * j], fmaf(v1, alv[2 * j + 1], sB));
                    rB = fmaf(v0, arv[2 * j], fmaf(v1, arv[2 * j + 1], rB));
                }
            }
            if (row < M) {
                uint32_t* dst = g_fth + (size_t)row * 64 + (n0 >> 1) + (lane & 3);
#pragma unroll
                for (int j = 0; j < 8; j++) dst[j * 4] = pk[j];
            }
            sA += __shfl_xor_sync(~0u, sA, 1); sA += __shfl_xor_sync(~0u, sA, 2);
            sB += __shfl_xor_sync(~0u, sB, 1); sB += __shfl_xor_sync(~0u, sB, 2);
            rA += __shfl_xor_sync(~0u, rA, 1); rA += __shfl_xor_sync(~0u, rA, 2);
            rB += __shfl_xor_sync(~0u, rB, 1); rB += __shfl_xor_sync(~0u, rB, 2);
            if ((lane & 3) == 0 && row < M) {
                g_el[row * 4 + hA]     = sA;
                g_el[row * 4 + hA + 1] = sB;
                g_er[row * 4 + hA]     = rA;
                g_er[row * 4 + hA + 1] = rB;
            }
        }
    }
}

// ---------------- 2) aggregation: 1 warp/node, half-warp per edge, FFMA2 -------
// (identical to round-10/11/12 passing version)
__global__ __launch_bounds__(256) void agg_kernel(const int* __restrict__ src,
                                                  float* __restrict__ out, int N) {
    int gid  = blockIdx.x * blockDim.x + threadIdx.x;
    int node = gid >> 5;
    int lane = gid & 31;
    if (node >= N) return;

    const int half = lane >> 4;       // 0/1: which edge of the pair
    const int sl   = lane & 15;       // feature slice: halves [8*sl, 8*sl+8)
    const int h    = sl >> 2;         // head of this slice

    int s = g_offs[node];
    int e = g_offs[node + 1];
    float er_h = g_er[node * 4 + h];

    float psum = 0.f;
    unsigned long long acc[4];
#pragma unroll
    for (int q = 0; q < 4; q++) acc[q] = 0ull;

    const uint4* ft = (const uint4*)g_fth;   // 16 uint4 per row
#pragma unroll 2
    for (int i = s + half; i < e; i += 2) {
        int sn = __ldg(src + i);
        float sc = __ldg(&g_el[sn * 4 + h]) + er_h;   // already in log2 domain
        sc = fmaxf(sc, NEG_SLOPE * sc);               // leaky commutes with +scale
        float p;
        asm("ex2.approx.f32 %0, %1;" : "=f"(p) : "f"(sc));
        psum += p;
        unsigned long long pp;
        asm("mov.b64 %0, {%1, %1};" : "=l"(pp) : "r"(__float_as_uint(p)));
        uint4 v = __ldg(&ft[(size_t)sn * 16 + sl]);
        const __half2* hv = (const __half2*)&v;
#pragma unroll
        for (int q = 0; q < 4; q++) {
            float2 f = __half22float2(hv[q]);
            unsigned long long ff;
            asm("mov.b64 %0, {%1, %2};" : "=l"(ff)
                : "r"(__float_as_uint(f.x)), "r"(__float_as_uint(f.y)));
            asm("fma.rn.f32x2 %0, %1, %2, %0;" : "+l"(acc[q]) : "l"(pp), "l"(ff));
        }
    }

    // combine the two half-warps
    psum += __shfl_xor_sync(~0u, psum, 16);
    float a[8];
#pragma unroll
    for (int q = 0; q < 4; q++) {
        uint32_t lo, hi;
        asm("mov.b64 {%0, %1}, %2;" : "=r"(lo), "=r"(hi) : "l"(acc[q]));
        a[2 * q]     = __uint_as_float(lo);
        a[2 * q + 1] = __uint_as_float(hi);
    }
#pragma unroll
    for (int q = 0; q < 8; q++) a[q] += __shfl_xor_sync(~0u, a[q], 16);

    if (half == 0) {
        float inv = (psum > 0.f) ? (1.f / psum) : 0.f;
        float* dst = out + (size_t)node * 128 + sl * 8;
        *(float4*)dst       = make_float4(a[0] * inv, a[1] * inv, a[2] * inv, a[3] * inv);
        *(float4*)(dst + 4) = make_float4(a[4] * inv, a[5] * inv, a[6] * inv, a[7] * inv);
    }
}

// ---------------- launch ----------------
extern "C" void kernel_launch(void* const* d_in, const int* in_sizes, int n_in,
                              void* d_out, int out_size) {
    const float* feat   = (const float*)d_in[0];
    const int*   src    = (const int*)d_in[1];
    const int*   dst    = (const int*)d_in[2];
    const float* W      = (const float*)d_in[3];
    const float* attn_l = (const float*)d_in[4];
    const float* attn_r = (const float*)d_in[5];
    float* out = (float*)d_out;

    int M = in_sizes[0] / 128;   // nodes
    int E = in_sizes[1];         // edges

    cudaFuncSetAttribute(gemm_mma_kernel, cudaFuncAttributeMaxDynamicSharedMemorySize, SM_TOTAL);

    int edgeBlocks = (E + 255) / 256;
    prep_kernel<<<64 + edgeBlocks, 256>>>(W, dst, M, E);
    gemm_mma_kernel<<<(M + 127) / 128, 256, SM_TOTAL>>>(feat, attn_l, attn_r, M);
    agg_kernel<<<((size_t)M * 32 + 255) / 256, 256>>>(src, out, M);
}

// round 14
// speedup vs baseline: 1.5908x; 1.0276x over previous
#include <cuda_runtime.h>
#include <cuda_bf16.h>
#include <cuda_fp16.h>
#include <math.h>
#include <stdint.h>

#define N_NODES_MAX 100000
#define NEG_SLOPE 0.2f
#define LOG2E 1.4426950408889634f

// ---------------- scratch (device globals: alloc-free) ----------------
__device__ float    g_el[N_NODES_MAX * 4];    // pre-scaled by LOG2E
__device__ float    g_er[N_NODES_MAX * 4];    // pre-scaled by LOG2E
__device__ int      g_offs[N_NODES_MAX + 1];
__device__ uint32_t g_fth[N_NODES_MAX * 64];  // fp16 ft rows: 64 uint32 = 128 half
__device__ uint4    g_Bh4[2048];              // fp16 B[n][k] image (128x128 = 32KB)

__device__ __forceinline__ uint32_t smem_u32(const void* p) {
    uint32_t a;
    asm("{ .reg .u64 t; cvta.to.shared.u64 t, %1; cvt.u32.u64 %0, t; }" : "=r"(a) : "l"(p));
    return a;
}

#define LDM4(r, addr) \
    asm volatile("ldmatrix.sync.aligned.m8n8.x4.shared.b16 {%0,%1,%2,%3}, [%4];" \
        : "=r"((r)[0]), "=r"((r)[1]), "=r"((r)[2]), "=r"((r)[3]) : "r"(addr))

#define MMA_F16(c, a, b) \
    asm volatile("mma.sync.aligned.m16n8k16.row.col.f32.f16.f16.f32 " \
        "{%0,%1,%2,%3}, {%4,%5,%6,%7}, {%8,%9}, {%0,%1,%2,%3};" \
        : "+f"((c)[0]), "+f"((c)[1]), "+f"((c)[2]), "+f"((c)[3]) \
        : "r"((a)[0]), "r"((a)[1]), "r"((a)[2]), "r"((a)[3]), "r"((b)[0]), "r"((b)[1]))

// smem: padded rows of 136 half = 272 B (17x16B -> conflict-free ldmatrix)
#define ROWB 272
#define SA    0
#define SB    (SA + 128 * ROWB)
#define SM_TOTAL (SB + 128 * ROWB)   // 69632 B -> 2 CTAs/SM

// ------- 0) prep: W -> fp16 B image (blocks 0..63) + offsets scatter (64..) ----
// dst sorted. Each offsets-thread owns 8 edges via two int4 loads; boundary
// compares fill offs[n]=i for gaps. offs[n] = first i with dst[i] >= n.
__global__ void prep_kernel(const float* __restrict__ W,
                            const int* __restrict__ dst, int N, int E) {
    int b = blockIdx.x;
    if (b < 64) {
        int idx = b * 256 + threadIdx.x;        // 0..16383
        int k = idx >> 7, n = idx & 127;
        ((__half*)g_Bh4)[n * 128 + k] = __float2half_rn(W[idx]);
        return;
    }
    int base = ((b - 64) * 256 + threadIdx.x) * 8;    // first edge of this group
    if (base >= E) return;

    int d[8];
    int cnt;
    if (base + 8 <= E && ((base & 3) == 0)) {
        int4 v0 = *(const int4*)(dst + base);
        int4 v1 = *(const int4*)(dst + base + 4);
        d[0] = v0.x; d[1] = v0.y; d[2] = v0.z; d[3] = v0.w;
        d[4] = v1.x; d[5] = v1.y; d[6] = v1.z; d[7] = v1.w;
        cnt = 8;
    } else {
        cnt = E - base; if (cnt > 8) cnt = 8;
        for (int k = 0; k < cnt; k++) d[k] = __ldg(dst + base + k);
        for (int k = cnt; k < 8; k++) d[k] = 0;
    }
    int prev = (base == 0) ? -1 : __ldg(dst + base - 1);
#pragma unroll
    for (int k = 0; k < 8; k++) {
        if (k < cnt) {
            for (int n = prev + 1; n <= d[k]; n++) g_offs[n] = base + k;
            prev = d[k];
        }
    }
    if (base + cnt >= E) {                        // this thread owns the last edge
        for (int n = prev + 1; n <= N; n++) g_offs[n] = E;
    }
}

// ---------------- 1) mma.sync single-term fp16 GEMM + fused ft / el / er -------
__global__ __launch_bounds__(256, 2) void gemm_mma_kernel(const float* __restrict__ A,
                                                          const float* __restrict__ attn_l,
                                                          const float* __restrict__ attn_r,
                                                          int M) {
    extern __shared__ char smem[];
    const uint32_t sb = smem_u32(smem);
    const int tid = threadIdx.x, wid = tid >> 5, lane = tid & 31;
    const int bm = blockIdx.x * 128;
    const bool full = (bm + 128 <= M);

    if (full) {
        // fast path: batch loads for MLP (8 B-LDGs + 8 A-LDGs in flight), no predicates
        uint4 bv[8];
#pragma unroll
        for (int i = 0; i < 8; i++) bv[i] = g_Bh4[tid + i * 256];
        float4 av4[8];
#pragma unroll
        for (int it = 0; it < 8; it++) {
            int idx = tid + it * 256;
            av4[it] = *(const float4*)(A + (size_t)(bm + (idx >> 5)) * 128 + (idx & 31) * 4);
        }
#pragma unroll
        for (int i = 0; i < 8; i++) {
            int t = tid + i * 256;
            *(uint4*)(smem + SB + (t >> 4) * ROWB + (t & 15) * 16) = bv[i];
        }
#pragma unroll
        for (int it = 0; it < 8; it++) {
            int idx = tid + it * 256;
            __half2 hA = __floats2half2_rn(av4[it].x, av4[it].y);
            __half2 hB = __floats2half2_rn(av4[it].z, av4[it].w);
            *(uint2*)(smem + SA + (idx >> 5) * ROWB + (idx & 31) * 8) =
                make_uint2(*(uint32_t*)&hA, *(uint32_t*)&hB);
        }
#pragma unroll
        for (int it = 8; it < 16; it++) {
            int idx = tid + it * 256;
            float4 v = *(const float4*)(A + (size_t)(bm + (idx >> 5)) * 128 + (idx & 31) * 4);
            __half2 hA = __floats2half2_rn(v.x, v.y);
            __half2 hB = __floats2half2_rn(v.z, v.w);
            *(uint2*)(smem + SA + (idx >> 5) * ROWB + (idx & 31) * 8) =
                make_uint2(*(uint32_t*)&hA, *(uint32_t*)&hB);
        }
    } else {
        for (int i = tid; i < 2048; i += 256) {
            int row = i >> 4, c = i & 15;
            *(uint4*)(smem + SB + row * ROWB + c * 16) = g_Bh4[i];
        }
#pragma unroll 4
        for (int it = 0; it < 16; it++) {
            int idx = tid + it * 256;
            int row = idx >> 5, c4 = (idx & 31) * 4;
            float4 v = make_float4(0.f, 0.f, 0.f, 0.f);
            if (bm + row < M) v = *(const float4*)(A + (size_t)(bm + row) * 128 + c4);
            __half2 hA = __floats2half2_rn(v.x, v.y);
            __half2 hB = __floats2half2_rn(v.z, v.w);
            *(uint2*)(smem + SA + row * ROWB + c4 * 2) = make_uint2(*(uint32_t*)&hA, *(uint32_t*)&hB);
        }
    }
    __syncthreads();

    const int wm = wid & 3, wn = wid >> 2;
    const int m0 = wm * 32, n0 = wn * 64;

    float acc[2][8][4];
#pragma unroll
    for (int i = 0; i < 2; i++)
#pragma unroll
        for (int j = 0; j < 8; j++)
#pragma unroll
            for (int q = 0; q < 4; q++) acc[i][j][q] = 0.f;

    // ldmatrix per-lane base addresses
    const uint32_t a_row = m0 + (lane & 15);
    const uint32_t a_off = a_row * ROWB + ((lane >> 4) << 4);
    const uint32_t b_row = n0 + (lane & 7) + ((lane >> 4) << 3);
    const uint32_t b_off = b_row * ROWB + (((lane >> 3) & 1) << 4);
    const uint32_t a_b = sb + SA + a_off;
    const uint32_t b_b = sb + SB + b_off;

#pragma unroll
    for (int ks = 0; ks < 8; ks++) {
        const uint32_t k0b = ks * 32;   // 16 cols * 2B
        uint32_t av[2][4], bh[8][2];
        LDM4(av[0], a_b + k0b);
        LDM4(av[1], a_b + 16 * ROWB + k0b);
#pragma unroll
        for (int jj = 0; jj < 4; jj++) {
            uint32_t r[4];
            LDM4(r, b_b + jj * 16 * ROWB + k0b);
            bh[2 * jj][0] = r[0]; bh[2 * jj][1] = r[1];
            bh[2 * jj + 1][0] = r[2]; bh[2 * jj + 1][1] = r[3];
        }
#pragma unroll
        for (int im = 0; im < 2; im++)
#pragma unroll
            for (int jn = 0; jn < 8; jn++)
                MMA_F16(acc[im][jn], av[im], bh[jn]);
    }

    // epilogue: fp16 ft + exact el/er (quad owns full 32-col head dot)
    // attn vectors pre-scaled by LOG2E so agg can use bare ex2.
    float alv[16], arv[16];
#pragma unroll
    for (int j = 0; j < 8; j++) {
        int c0 = n0 + j * 8 + 2 * (lane & 3);
        alv[2 * j] = __ldg(attn_l + c0) * LOG2E; alv[2 * j + 1] = __ldg(attn_l + c0 + 1) * LOG2E;
        arv[2 * j] = __ldg(attn_r + c0) * LOG2E; arv[2 * j + 1] = __ldg(attn_r + c0 + 1) * LOG2E;
    }
    const int hA = n0 >> 5;            // heads hA, hA+1
#pragma unroll
    for (int im = 0; im < 2; im++) {
#pragma unroll
        for (int hf = 0; hf < 2; hf++) {
            int row = bm + m0 + im * 16 + (lane >> 2) + hf * 8;
            float sA = 0.f, sB = 0.f, rA = 0.f, rB = 0.f;
            uint32_t pk[8];
#pragma unroll
            for (int j = 0; j < 8; j++) {
                float v0 = acc[im][j][hf * 2], v1 = acc[im][j][hf * 2 + 1];
                __half2 hh = __floats2half2_rn(v0, v1);
                pk[j] = *(uint32_t*)&hh;
                if (j < 4) {
                    sA = fmaf(v0, alv[2 * j], fmaf(v1, alv[2 * j + 1], sA));
                    rA = fmaf(v0, arv[2 * j], fmaf(v1, arv[2 * j + 1], rA));
                } else {
                    sB = fmaf(v0, alv[2 * j], fmaf(v1, alv[2 * j + 1], sB));
                    rB = fmaf(v0, arv[2 * j], fmaf(v1, arv[2 * j + 1], rB));
                }
            }
            if (row < M) {
                uint32_t* dst = g_fth + (size_t)row * 64 + (n0 >> 1) + (lane & 3);
#pragma unroll
                for (int j = 0; j < 8; j++) dst[j * 4] = pk[j];
            }
            sA += __shfl_xor_sync(~0u, sA, 1); sA += __shfl_xor_sync(~0u, sA, 2);
            sB += __shfl_xor_sync(~0u, sB, 1); sB += __shfl_xor_sync(~0u, sB, 2);
            rA += __shfl_xor_sync(~0u, rA, 1); rA += __shfl_xor_sync(~0u, rA, 2);
            rB += __shfl_xor_sync(~0u, rB, 1); rB += __shfl_xor_sync(~0u, rB, 2);
            if ((lane & 3) == 0 && row < M) {
                g_el[row * 4 + hA]     = sA;
                g_el[row * 4 + hA + 1] = sB;
                g_er[row * 4 + hA]     = rA;
                g_er[row * 4 + hA + 1] = rB;
            }
        }
    }
}

// ---------------- 2) aggregation: 1 warp/node, half-warp per edge, FFMA2 -------
// (identical to round-10..13 passing version)
__global__ __launch_bounds__(256) void agg_kernel(const int* __restrict__ src,
                                                  float* __restrict__ out, int N) {
    int gid  = blockIdx.x * blockDim.x + threadIdx.x;
    int node = gid >> 5;
    int lane = gid & 31;
    if (node >= N) return;

    const int half = lane >> 4;       // 0/1: which edge of the pair
    const int sl   = lane & 15;       // feature slice: halves [8*sl, 8*sl+8)
    const int h    = sl >> 2;         // head of this slice

    int s = g_offs[node];
    int e = g_offs[node + 1];
    float er_h = g_er[node * 4 + h];

    float psum = 0.f;
    unsigned long long acc[4];
#pragma unroll
    for (int q = 0; q < 4; q++) acc[q] = 0ull;

    const uint4* ft = (const uint4*)g_fth;   // 16 uint4 per row
#pragma unroll 2
    for (int i = s + half; i < e; i += 2) {
        int sn = __ldg(src + i);
        float sc = __ldg(&g_el[sn * 4 + h]) + er_h;   // already in log2 domain
        sc = fmaxf(sc, NEG_SLOPE * sc);               // leaky commutes with +scale
        float p;
        asm("ex2.approx.f32 %0, %1;" : "=f"(p) : "f"(sc));
        psum += p;
        unsigned long long pp;
        asm("mov.b64 %0, {%1, %1};" : "=l"(pp) : "r"(__float_as_uint(p)));
        uint4 v = __ldg(&ft[(size_t)sn * 16 + sl]);
        const __half2* hv = (const __half2*)&v;
#pragma unroll
        for (int q = 0; q < 4; q++) {
            float2 f = __half22float2(hv[q]);
            unsigned long long ff;
            asm("mov.b64 %0, {%1, %2};" : "=l"(ff)
                : "r"(__float_as_uint(f.x)), "r"(__float_as_uint(f.y)));
            asm("fma.rn.f32x2 %0, %1, %2, %0;" : "+l"(acc[q]) : "l"(pp), "l"(ff));
        }
    }

    // combine the two half-warps
    psum += __shfl_xor_sync(~0u, psum, 16);
    float a[8];
#pragma unroll
    for (int q = 0; q < 4; q++) {
        uint32_t lo, hi;
        asm("mov.b64 {%0, %1}, %2;" : "=r"(lo), "=r"(hi) : "l"(acc[q]));
        a[2 * q]     = __uint_as_float(lo);
        a[2 * q + 1] = __uint_as_float(hi);
    }
#pragma unroll
    for (int q = 0; q < 8; q++) a[q] += __shfl_xor_sync(~0u, a[q], 16);

    if (half == 0) {
        float inv = (psum > 0.f) ? (1.f / psum) : 0.f;
        float* dst = out + (size_t)node * 128 + sl * 8;
        *(float4*)dst       = make_float4(a[0] * inv, a[1] * inv, a[2] * inv, a[3] * inv);
        *(float4*)(dst + 4) = make_float4(a[4] * inv, a[5] * inv, a[6] * inv, a[7] * inv);
    }
}

// ---------------- launch ----------------
extern "C" void kernel_launch(void* const* d_in, const int* in_sizes, int n_in,
                              void* d_out, int out_size) {
    const float* feat   = (const float*)d_in[0];
    const int*   src    = (const int*)d_in[1];
    const int*   dst    = (const int*)d_in[2];
    const float* W      = (const float*)d_in[3];
    const float* attn_l = (const float*)d_in[4];
    const float* attn_r = (const float*)d_in[5];
    float* out = (float*)d_out;

    int M = in_sizes[0] / 128;   // nodes
    int E = in_sizes[1];         // edges

    cudaFuncSetAttribute(gemm_mma_kernel, cudaFuncAttributeMaxDynamicSharedMemorySize, SM_TOTAL);

    int groupBlocks = ((E + 7) / 8 + 255) / 256;
    prep_kernel<<<64 + groupBlocks, 256>>>(W, dst, M, E);
    gemm_mma_kernel<<<(M + 127) / 128, 256, SM_TOTAL>>>(feat, attn_l, attn_r, M);
    agg_kernel<<<((size_t)M * 32 + 255) / 256, 256>>>(src, out, M);
}